// round 5
// baseline (speedup 1.0000x reference)
#include <cuda_runtime.h>
#include <cstdint>

#define C_DIM 1024
#define B_DIM 4
#define T_DIM 2048
#define H_DIM 16
#define HD    64
#define M_TOT (B_DIM * T_DIM)   // 8192
#define N_TOT (3 * C_DIM)       // 3072

// Q/K/V scratch in [B,H,T,D] layout
__device__ float g_q[(size_t)M_TOT * C_DIM];
__device__ float g_k[(size_t)M_TOT * C_DIM];
__device__ float g_v[(size_t)M_TOT * C_DIM];

__device__ __forceinline__ uint32_t f2tf(float f) {
    uint32_t u;
    asm("cvt.rna.tf32.f32 %0, %1;" : "=r"(u) : "f"(f));
    return u;
}

__device__ __forceinline__ void mma_tf32(float c[4], const uint32_t a[4],
                                         const uint32_t b[2]) {
    asm volatile(
        "mma.sync.aligned.m16n8k8.row.col.f32.tf32.tf32.f32 "
        "{%0,%1,%2,%3}, {%4,%5,%6,%7}, {%8,%9}, {%0,%1,%2,%3};"
        : "+f"(c[0]), "+f"(c[1]), "+f"(c[2]), "+f"(c[3])
        : "r"(a[0]), "r"(a[1]), "r"(a[2]), "r"(a[3]), "r"(b[0]), "r"(b[1]));
}

// ---------------------------------------------------------------------------
// QKV GEMM (TF32, software-pipelined):
//   qkv[m,o] = x[m,:] . W[o,:] + b[o], scattered into g_q/g_k/g_v [B,H,T,D].
// CTA tile 128x128, k-tile 16, double-buffered smem, register prefetch,
// ONE __syncthreads per k-tile. 8 warps (2M x 4N), warp tile 64x32.
// ---------------------------------------------------------------------------
__global__ __launch_bounds__(256) void qkv_gemm_tf32(
    const float* __restrict__ x,
    const float* __restrict__ W,
    const float* __restrict__ b)
{
    // pad 20: frag reads hit banks (20*(lane>>2)+(lane&3))%32 -> all distinct
    __shared__ uint32_t As[2][128][20];
    __shared__ uint32_t Bs[2][128][20];

    const int tid  = threadIdx.x;
    const int lane = tid & 31;
    const int warp = tid >> 5;
    const int wm = warp >> 2;          // 0..1
    const int wn = warp & 3;           // 0..3
    const int m0 = blockIdx.y * 128;
    const int n0 = blockIdx.x * 128;

    const int lrow = tid >> 1;             // 0..127
    const int lcol = (tid & 1) * 8;        // 0 or 8
    const float* ap = x + (size_t)(m0 + lrow) * C_DIM + lcol;
    const float* bp = W + (size_t)(n0 + lrow) * C_DIM + lcol;

    float acc[4][4][4] = {};

    // register prefetch of k-tile 0
    float4 ar0 = *(const float4*)(ap);
    float4 ar1 = *(const float4*)(ap + 4);
    float4 br0 = *(const float4*)(bp);
    float4 br1 = *(const float4*)(bp + 4);

    #pragma unroll 1
    for (int kt = 0; kt < 64; kt++) {
        const int st = kt & 1;

        // Stage current tile (convert rna -> tf32, vectorized stores).
        // Safe without a pre-sync: stage st was last READ at iteration kt-2,
        // and the sync at iteration kt-1 ordered those reads before us.
        {
            uint4 v;
            v.x = f2tf(ar0.x); v.y = f2tf(ar0.y); v.z = f2tf(ar0.z); v.w = f2tf(ar0.w);
            *(uint4*)&As[st][lrow][lcol] = v;
            v.x = f2tf(ar1.x); v.y = f2tf(ar1.y); v.z = f2tf(ar1.z); v.w = f2tf(ar1.w);
            *(uint4*)&As[st][lrow][lcol + 4] = v;
            v.x = f2tf(br0.x); v.y = f2tf(br0.y); v.z = f2tf(br0.z); v.w = f2tf(br0.w);
            *(uint4*)&Bs[st][lrow][lcol] = v;
            v.x = f2tf(br1.x); v.y = f2tf(br1.y); v.z = f2tf(br1.z); v.w = f2tf(br1.w);
            *(uint4*)&Bs[st][lrow][lcol + 4] = v;
        }
        __syncthreads();

        // Issue next tile's global loads (latency hidden under compute below)
        if (kt < 63) {
            const float* apn = ap + (kt + 1) * 16;
            const float* bpn = bp + (kt + 1) * 16;
            ar0 = *(const float4*)(apn);
            ar1 = *(const float4*)(apn + 4);
            br0 = *(const float4*)(bpn);
            br1 = *(const float4*)(bpn + 4);
        }

        // Compute on stage st: two k8 steps
        #pragma unroll
        for (int ks = 0; ks < 16; ks += 8) {
            uint32_t af[4][4];
            #pragma unroll
            for (int mt = 0; mt < 4; mt++) {
                const int r = wm * 64 + mt * 16 + (lane >> 2);
                const int c = ks + (lane & 3);
                af[mt][0] = As[st][r][c];     af[mt][1] = As[st][r + 8][c];
                af[mt][2] = As[st][r][c + 4]; af[mt][3] = As[st][r + 8][c + 4];
            }
            uint32_t bf[4][2];
            #pragma unroll
            for (int nt = 0; nt < 4; nt++) {
                const int r = wn * 32 + nt * 8 + (lane >> 2);
                const int c = ks + (lane & 3);
                bf[nt][0] = Bs[st][r][c];
                bf[nt][1] = Bs[st][r][c + 4];
            }
            #pragma unroll
            for (int mt = 0; mt < 4; mt++)
                #pragma unroll
                for (int nt = 0; nt < 4; nt++)
                    mma_tf32(acc[mt][nt], af[mt], bf[nt]);
        }
    }

    // Epilogue: bias + scatter to [B,H,T,D]
    const int which = n0 >> 10;                 // tile never straddles q/k/v
    float* dst = (which == 0) ? g_q : (which == 1) ? g_k : g_v;
    const int bq = m0 >> 11;
    const int t0 = m0 & (T_DIM - 1);
    const int h  = (((n0 & 1023) + wn * 32) >> 6);  // constant per warp

    #pragma unroll
    for (int nt = 0; nt < 4; nt++) {
        const int ncol = wn * 32 + nt * 8 + 2 * (lane & 3);
        const float2 bias = *(const float2*)(b + n0 + ncol);
        const int d = ncol & 63;
        const size_t rowbase = (size_t)(bq * H_DIM + h) * T_DIM;
        #pragma unroll
        for (int mt = 0; mt < 4; mt++) {
            const int t = t0 + wm * 64 + mt * 16 + (lane >> 2);
            float2 v0 = { acc[mt][nt][0] + bias.x, acc[mt][nt][1] + bias.y };
            float2 v1 = { acc[mt][nt][2] + bias.x, acc[mt][nt][3] + bias.y };
            *(float2*)(dst + (rowbase + t) * HD + d)       = v0;
            *(float2*)(dst + (rowbase + t + 8) * HD + d)   = v1;
        }
    }
}

// ---------------------------------------------------------------------------
// Flash attention (TF32 tensor cores) — unchanged from round 4.
// CTA: 64 q-rows, 4 warps (16 rows each). KV tiles of 64.
// ---------------------------------------------------------------------------
#define KS_PAD 68   // bank = (4*row'+col')%32 for frag reads: conflict-free
#define VS_PAD 72   // bank = (8*row'+col')%32 for frag reads: conflict-free
#define SMEM_U32 (64 * KS_PAD + 64 * VS_PAD + 64 * KS_PAD)
#define ATTN_SMEM_BYTES (SMEM_U32 * 4)

__global__ __launch_bounds__(128) void attn_tf32(float* __restrict__ out)
{
    extern __shared__ uint32_t sm[];
    uint32_t (*Ks)[KS_PAD] = (uint32_t(*)[KS_PAD])(sm);
    uint32_t (*Vs)[VS_PAD] = (uint32_t(*)[VS_PAD])(sm + 64 * KS_PAD);
    uint32_t (*Ps)[KS_PAD] = (uint32_t(*)[KS_PAD])(sm + 64 * KS_PAD + 64 * VS_PAD);

    const int tid  = threadIdx.x;
    const int lane = tid & 31;
    const int warp = tid >> 5;
    const int qt = blockIdx.x;      // q tile 0..31
    const int bh = blockIdx.y;      // 0..63

    const size_t hoff = (size_t)bh * T_DIM * HD;
    const float* Qg = g_q + hoff;
    const float* Kg = g_k + hoff;
    const float* Vg = g_v + hoff;

    // Stage Q tile (scaled by 1/8) through Ps, then pull A-frags to registers.
    {
        const int row = tid >> 1;
        const int col = (tid & 1) * 32;
        const float* qp = Qg + (size_t)(qt * 64 + row) * HD + col;
        #pragma unroll
        for (int i = 0; i < 8; i++) {
            float4 v = *(const float4*)(qp + i * 4);
            Ps[row][col + i * 4 + 0] = f2tf(v.x * 0.125f);
            Ps[row][col + i * 4 + 1] = f2tf(v.y * 0.125f);
            Ps[row][col + i * 4 + 2] = f2tf(v.z * 0.125f);
            Ps[row][col + i * 4 + 3] = f2tf(v.w * 0.125f);
        }
    }
    __syncthreads();
    uint32_t qa[8][4];
    {
        const int r = warp * 16 + (lane >> 2);
        #pragma unroll
        for (int k = 0; k < 8; k++) {
            const int c = k * 8 + (lane & 3);
            qa[k][0] = Ps[r][c];     qa[k][1] = Ps[r + 8][c];
            qa[k][2] = Ps[r][c + 4]; qa[k][3] = Ps[r + 8][c + 4];
        }
    }

    float oa[8][4] = {};
    float mrow0 = -1e30f, mrow1 = -1e30f, l0 = 0.0f, l1 = 0.0f;
    const int gr0 = qt * 64 + warp * 16 + (lane >> 2);
    const int gr1 = gr0 + 8;

    for (int kt = 0; kt <= qt; kt++) {
        __syncthreads();  // Ks/Vs consumers from previous iter done, qa loads done
        {
            const int row = tid >> 1;
            const int col = (tid & 1) * 32;
            const float* kp = Kg + (size_t)(kt * 64 + row) * HD + col;
            const float* vp = Vg + (size_t)(kt * 64 + row) * HD + col;
            #pragma unroll
            for (int i = 0; i < 8; i++) {
                float4 kv = *(const float4*)(kp + i * 4);
                Ks[row][col + i * 4 + 0] = f2tf(kv.x);
                Ks[row][col + i * 4 + 1] = f2tf(kv.y);
                Ks[row][col + i * 4 + 2] = f2tf(kv.z);
                Ks[row][col + i * 4 + 3] = f2tf(kv.w);
                float4 vv = *(const float4*)(vp + i * 4);
                Vs[row][col + i * 4 + 0] = f2tf(vv.x);
                Vs[row][col + i * 4 + 1] = f2tf(vv.y);
                Vs[row][col + i * 4 + 2] = f2tf(vv.z);
                Vs[row][col + i * 4 + 3] = f2tf(vv.w);
            }
        }
        __syncthreads();

        // S = Q @ K^T
        float s[8][4] = {};
        #pragma unroll
        for (int k = 0; k < 8; k++) {
            #pragma unroll
            for (int j = 0; j < 8; j++) {
                uint32_t bfr[2];
                const int rr = j * 8 + (lane >> 2);
                const int cc = k * 8 + (lane & 3);
                bfr[0] = Ks[rr][cc];
                bfr[1] = Ks[rr][cc + 4];
                mma_tf32(s[j], qa[k], bfr);
            }
        }

        // Causal mask (diagonal tile only)
        if (kt == qt) {
            #pragma unroll
            for (int j = 0; j < 8; j++) {
                const int c0 = kt * 64 + j * 8 + 2 * (lane & 3);
                if (c0     > gr0) s[j][0] = -1e30f;
                if (c0 + 1 > gr0) s[j][1] = -1e30f;
                if (c0     > gr1) s[j][2] = -1e30f;
                if (c0 + 1 > gr1) s[j][3] = -1e30f;
            }
        }

        // Online softmax in registers (quad = lanes sharing lane>>2)
        float mx0 = -1e30f, mx1 = -1e30f;
        #pragma unroll
        for (int j = 0; j < 8; j++) {
            mx0 = fmaxf(mx0, fmaxf(s[j][0], s[j][1]));
            mx1 = fmaxf(mx1, fmaxf(s[j][2], s[j][3]));
        }
        mx0 = fmaxf(mx0, __shfl_xor_sync(0xffffffff, mx0, 1));
        mx0 = fmaxf(mx0, __shfl_xor_sync(0xffffffff, mx0, 2));
        mx1 = fmaxf(mx1, __shfl_xor_sync(0xffffffff, mx1, 1));
        mx1 = fmaxf(mx1, __shfl_xor_sync(0xffffffff, mx1, 2));

        const float nm0 = fmaxf(mrow0, mx0);
        const float nm1 = fmaxf(mrow1, mx1);
        const float corr0 = __expf(mrow0 - nm0);
        const float corr1 = __expf(mrow1 - nm1);
        mrow0 = nm0; mrow1 = nm1;

        float sum0 = 0.0f, sum1 = 0.0f;
        #pragma unroll
        for (int j = 0; j < 8; j++) {
            s[j][0] = __expf(s[j][0] - nm0); sum0 += s[j][0];
            s[j][1] = __expf(s[j][1] - nm0); sum0 += s[j][1];
            s[j][2] = __expf(s[j][2] - nm1); sum1 += s[j][2];
            s[j][3] = __expf(s[j][3] - nm1); sum1 += s[j][3];
        }
        sum0 += __shfl_xor_sync(0xffffffff, sum0, 1);
        sum0 += __shfl_xor_sync(0xffffffff, sum0, 2);
        sum1 += __shfl_xor_sync(0xffffffff, sum1, 1);
        sum1 += __shfl_xor_sync(0xffffffff, sum1, 2);
        l0 = l0 * corr0 + sum0;
        l1 = l1 * corr1 + sum1;

        #pragma unroll
        for (int j = 0; j < 8; j++) {
            oa[j][0] *= corr0; oa[j][1] *= corr0;
            oa[j][2] *= corr1; oa[j][3] *= corr1;
        }

        // Store P (warp-private rows of Ps)
        {
            const int r = warp * 16 + (lane >> 2);
            #pragma unroll
            for (int j = 0; j < 8; j++) {
                const int c = j * 8 + 2 * (lane & 3);
                Ps[r][c]         = f2tf(s[j][0]);
                Ps[r][c + 1]     = f2tf(s[j][1]);
                Ps[r + 8][c]     = f2tf(s[j][2]);
                Ps[r + 8][c + 1] = f2tf(s[j][3]);
            }
        }
        __syncwarp();

        // O += P @ V
        #pragma unroll
        for (int k2 = 0; k2 < 8; k2++) {
            uint32_t af[4];
            const int r = warp * 16 + (lane >> 2);
            const int c = k2 * 8 + (lane & 3);
            af[0] = Ps[r][c];     af[1] = Ps[r + 8][c];
            af[2] = Ps[r][c + 4]; af[3] = Ps[r + 8][c + 4];
            #pragma unroll
            for (int j = 0; j < 8; j++) {
                uint32_t bfr[2];
                const int vr = k2 * 8 + (lane & 3);
                const int vc = j * 8 + (lane >> 2);
                bfr[0] = Vs[vr][vc];
                bfr[1] = Vs[vr + 4][vc];
                mma_tf32(oa[j], af, bfr);
            }
        }
    }

    // Epilogue: normalize and write [B,T,C]
    const float inv0 = 1.0f / l0;
    const float inv1 = 1.0f / l1;
    const int bq = bh >> 4;
    const int h  = bh & 15;
    const int trow = qt * 64 + warp * 16 + (lane >> 2);
    #pragma unroll
    for (int j = 0; j < 8; j++) {
        const int d = j * 8 + 2 * (lane & 3);
        float2 v0 = { oa[j][0] * inv0, oa[j][1] * inv0 };
        float2 v1 = { oa[j][2] * inv1, oa[j][3] * inv1 };
        *(float2*)(out + (size_t)(bq * T_DIM + trow) * C_DIM + h * HD + d)     = v0;
        *(float2*)(out + (size_t)(bq * T_DIM + trow + 8) * C_DIM + h * HD + d) = v1;
    }
}

// ---------------------------------------------------------------------------
extern "C" void kernel_launch(void* const* d_in, const int* in_sizes, int n_in,
                              void* d_out, int out_size)
{
    const float* x = (const float*)d_in[0];   // [4, 2048, 1024]
    const float* W = (const float*)d_in[1];   // [3072, 1024]
    const float* b = (const float*)d_in[2];   // [3072]
    float* out = (float*)d_out;               // [4, 2048, 1024]

    cudaFuncSetAttribute(attn_tf32, cudaFuncAttributeMaxDynamicSharedMemorySize,
                         ATTN_SMEM_BYTES);

    qkv_gemm_tf32<<<dim3(N_TOT / 128, M_TOT / 128), 256>>>(x, W, b);
    attn_tf32<<<dim3(T_DIM / 64, B_DIM * H_DIM), 128, ATTN_SMEM_BYTES>>>(out);
}

// round 7
// speedup vs baseline: 1.1245x; 1.1245x over previous
#include <cuda_runtime.h>
#include <cstdint>

#define C_DIM 1024
#define B_DIM 4
#define T_DIM 2048
#define H_DIM 16
#define HD    64
#define M_TOT (B_DIM * T_DIM)   // 8192
#define N_TOT (3 * C_DIM)       // 3072

// Q/K/V scratch in [B,H,T,D] layout
__device__ float g_q[(size_t)M_TOT * C_DIM];
__device__ float g_k[(size_t)M_TOT * C_DIM];
__device__ float g_v[(size_t)M_TOT * C_DIM];

__device__ __forceinline__ uint32_t f2tf(float f) {
    uint32_t u;
    asm("cvt.rna.tf32.f32 %0, %1;" : "=r"(u) : "f"(f));
    return u;
}

__device__ __forceinline__ float ex2(float x) {
    float y;
    asm("ex2.approx.f32 %0, %1;" : "=f"(y) : "f"(x));
    return y;
}

__device__ __forceinline__ void mma_tf32(float c[4], const uint32_t a[4],
                                         uint32_t b0, uint32_t b1) {
    asm volatile(
        "mma.sync.aligned.m16n8k8.row.col.f32.tf32.tf32.f32 "
        "{%0,%1,%2,%3}, {%4,%5,%6,%7}, {%8,%9}, {%0,%1,%2,%3};"
        : "+f"(c[0]), "+f"(c[1]), "+f"(c[2]), "+f"(c[3])
        : "r"(a[0]), "r"(a[1]), "r"(a[2]), "r"(a[3]), "r"(b0), "r"(b1));
}

// ldmatrix x4 (b16 view of tf32 data: each 16B chunk = 4 tf32 = one "row")
__device__ __forceinline__ void ldsm4(uint32_t& d0, uint32_t& d1,
                                      uint32_t& d2, uint32_t& d3,
                                      uint32_t addr) {
    asm volatile("ldmatrix.sync.aligned.m8n8.x4.shared.b16 {%0,%1,%2,%3}, [%4];"
                 : "=r"(d0), "=r"(d1), "=r"(d2), "=r"(d3) : "r"(addr));
}

__device__ __forceinline__ uint32_t smem_u32(const void* p) {
    uint32_t a;
    asm("{ .reg .u64 t; cvta.to.shared.u64 t, %1; cvt.u32.u64 %0, t; }"
        : "=r"(a) : "l"(p));
    return a;
}

// ---------------------------------------------------------------------------
// QKV GEMM (TF32 mma.sync + ldmatrix fragment loads).
// CTA tile 128x128, k-tile 16, 8 warps (2M x 4N), warp tile 64x32.
// ---------------------------------------------------------------------------
#define GPAD 20

__global__ __launch_bounds__(256) void qkv_gemm_tf32(
    const float* __restrict__ x,
    const float* __restrict__ W,
    const float* __restrict__ b)
{
    __shared__ uint32_t As[128][GPAD];
    __shared__ uint32_t Bs[128][GPAD];

    const int tid  = threadIdx.x;
    const int lane = tid & 31;
    const int warp = tid >> 5;
    const int wm = warp >> 2;          // 0..1
    const int wn = warp & 3;           // 0..3
    const int m0 = blockIdx.y * 128;
    const int n0 = blockIdx.x * 128;

    const uint32_t aBase = smem_u32(As);
    const uint32_t bBase = smem_u32(Bs);

    // A-frag ldmatrix lane offset (pad GPAD), bytes:
    //   row = (lane&7) + ((lane>>3)&1)*8 ; col = (lane>>4)*4
    const uint32_t offA = ((((lane & 7) + ((lane >> 3) & 1) * 8) * GPAD)
                           + (lane >> 4) * 4) * 4;
    // B row-pair ldmatrix offset: row = (lane&7) + (lane>>4)*8 ; col = ((lane>>3)&1)*4
    const uint32_t offBP = ((((lane & 7) + (lane >> 4) * 8) * GPAD)
                            + ((lane >> 3) & 1) * 4) * 4;

    const int lrow = tid >> 1;             // 0..127
    const int lcol = (tid & 1) * 8;        // 0 or 8
    const float* ap = x + (size_t)(m0 + lrow) * C_DIM + lcol;
    const float* bp = W + (size_t)(n0 + lrow) * C_DIM + lcol;

    float acc[4][4][4] = {};

    for (int k0 = 0; k0 < C_DIM; k0 += 16) {
        float4 av0 = *(const float4*)(ap + k0);
        float4 av1 = *(const float4*)(ap + k0 + 4);
        float4 bv0 = *(const float4*)(bp + k0);
        float4 bv1 = *(const float4*)(bp + k0 + 4);
        __syncthreads();
        {
            uint4 v;
            v.x = f2tf(av0.x); v.y = f2tf(av0.y); v.z = f2tf(av0.z); v.w = f2tf(av0.w);
            *(uint4*)&As[lrow][lcol] = v;
            v.x = f2tf(av1.x); v.y = f2tf(av1.y); v.z = f2tf(av1.z); v.w = f2tf(av1.w);
            *(uint4*)&As[lrow][lcol + 4] = v;
            v.x = f2tf(bv0.x); v.y = f2tf(bv0.y); v.z = f2tf(bv0.z); v.w = f2tf(bv0.w);
            *(uint4*)&Bs[lrow][lcol] = v;
            v.x = f2tf(bv1.x); v.y = f2tf(bv1.y); v.z = f2tf(bv1.z); v.w = f2tf(bv1.w);
            *(uint4*)&Bs[lrow][lcol + 4] = v;
        }
        __syncthreads();

        #pragma unroll
        for (int ks = 0; ks < 16; ks += 8) {
            uint32_t af[4][4];
            #pragma unroll
            for (int mt = 0; mt < 4; mt++) {
                ldsm4(af[mt][0], af[mt][1], af[mt][2], af[mt][3],
                      aBase + ((wm * 64 + mt * 16) * GPAD + ks) * 4 + offA);
            }
            uint32_t bf[4][2];
            ldsm4(bf[0][0], bf[0][1], bf[1][0], bf[1][1],
                  bBase + ((wn * 32) * GPAD + ks) * 4 + offBP);
            ldsm4(bf[2][0], bf[2][1], bf[3][0], bf[3][1],
                  bBase + ((wn * 32 + 16) * GPAD + ks) * 4 + offBP);
            #pragma unroll
            for (int mt = 0; mt < 4; mt++)
                #pragma unroll
                for (int nt = 0; nt < 4; nt++)
                    mma_tf32(acc[mt][nt], af[mt], bf[nt][0], bf[nt][1]);
        }
    }

    // Epilogue: bias + scatter to [B,H,T,D]
    const int which = n0 >> 10;
    float* dst = (which == 0) ? g_q : (which == 1) ? g_k : g_v;
    const int bq = m0 >> 11;
    const int t0 = m0 & (T_DIM - 1);
    const int h  = (((n0 & 1023) + wn * 32) >> 6);

    #pragma unroll
    for (int nt = 0; nt < 4; nt++) {
        const int ncol = wn * 32 + nt * 8 + 2 * (lane & 3);
        const float2 bias = *(const float2*)(b + n0 + ncol);
        const int d = ncol & 63;
        const size_t rowbase = (size_t)(bq * H_DIM + h) * T_DIM;
        #pragma unroll
        for (int mt = 0; mt < 4; mt++) {
            const int t = t0 + wm * 64 + mt * 16 + (lane >> 2);
            float2 v0 = { acc[mt][nt][0] + bias.x, acc[mt][nt][1] + bias.y };
            float2 v1 = { acc[mt][nt][2] + bias.x, acc[mt][nt][3] + bias.y };
            *(float2*)(dst + (rowbase + t) * HD + d)       = v0;
            *(float2*)(dst + (rowbase + t + 8) * HD + d)   = v1;
        }
    }
}

// ---------------------------------------------------------------------------
// Flash attention (TF32 mma.sync + ldmatrix fragments, V staged transposed).
// CTA: 64 q-rows, 4 warps (16 rows each). KV tiles of 64.
// smem: Ks[64][68] (also used to stage Q), Vt[64][68], Ps[64][68].
// ---------------------------------------------------------------------------
#define APAD 68
#define SMEM_U32 (3 * 64 * APAD)
#define ATTN_SMEM_BYTES (SMEM_U32 * 4)
// 1/8 * log2(e): softmax computed in base-2 domain
#define QSCALE 0.1803368801111204f

__global__ __launch_bounds__(128) void attn_tf32(float* __restrict__ out)
{
    extern __shared__ uint32_t sm[];
    uint32_t (*Ks)[APAD] = (uint32_t(*)[APAD])(sm);
    uint32_t (*Vt)[APAD] = (uint32_t(*)[APAD])(sm + 64 * APAD);
    uint32_t (*Ps)[APAD] = (uint32_t(*)[APAD])(sm + 2 * 64 * APAD);

    const int tid  = threadIdx.x;
    const int lane = tid & 31;
    const int warp = tid >> 5;
    const int qt = (gridDim.x - 1) - blockIdx.x;  // heavy tiles first
    const int bh = blockIdx.y;

    const uint32_t ksBase = smem_u32(Ks);
    const uint32_t vtBase = smem_u32(Vt);
    const uint32_t psBase = smem_u32(Ps);

    // ldmatrix lane offsets (bytes), pad APAD
    const uint32_t offA = ((((lane & 7) + ((lane >> 3) & 1) * 8) * APAD)
                           + (lane >> 4) * 4) * 4;
    const uint32_t offB = (((lane & 7) * APAD) + (lane >> 3) * 4) * 4;

    const size_t hoff = (size_t)bh * T_DIM * HD;
    const float* Qg = g_q + hoff;
    const float* Kg = g_k + hoff;
    const float* Vg = g_v + hoff;

    const int srow = tid >> 1;           // 0..63
    const int ch   = (tid & 1) * 32;     // 0 or 32

    // ---- Stage Q (scaled) into Ks, then pull qa fragments --------------------
    {
        const float* qp = Qg + (size_t)(qt * 64 + srow) * HD + ch;
        #pragma unroll
        for (int i = 0; i < 8; i++) {
            float4 v = *(const float4*)(qp + i * 4);
            uint4 u;
            u.x = f2tf(v.x * QSCALE); u.y = f2tf(v.y * QSCALE);
            u.z = f2tf(v.z * QSCALE); u.w = f2tf(v.w * QSCALE);
            *(uint4*)&Ks[srow][ch + i * 4] = u;
        }
    }
    __syncthreads();
    uint32_t qa[8][4];
    #pragma unroll
    for (int k = 0; k < 8; k++) {
        ldsm4(qa[k][0], qa[k][1], qa[k][2], qa[k][3],
              ksBase + ((warp * 16) * APAD + k * 8) * 4 + offA);
    }
    __syncthreads();   // qa read before Ks is overwritten with K

    float oa[8][4] = {};
    float mrow0 = -1e30f, mrow1 = -1e30f, l0 = 0.0f, l1 = 0.0f;
    const int gr0 = qt * 64 + warp * 16 + (lane >> 2);
    const int gr1 = gr0 + 8;

    for (int kt = 0; kt <= qt; kt++) {
        if (kt) __syncthreads();   // prior readers of Ks/Vt/Ps done
        // ---- stage K (row-major) and V (transposed) ----
        {
            const float* kp = Kg + (size_t)(kt * 64 + srow) * HD + ch;
            const float* vp = Vg + (size_t)(kt * 64 + srow) * HD + ch;
            #pragma unroll
            for (int i = 0; i < 8; i++) {
                float4 kv = *(const float4*)(kp + i * 4);
                uint4 u;
                u.x = f2tf(kv.x); u.y = f2tf(kv.y);
                u.z = f2tf(kv.z); u.w = f2tf(kv.w);
                *(uint4*)&Ks[srow][ch + i * 4] = u;
                float4 vv = *(const float4*)(vp + i * 4);
                Vt[ch + i * 4 + 0][srow] = f2tf(vv.x);
                Vt[ch + i * 4 + 1][srow] = f2tf(vv.y);
                Vt[ch + i * 4 + 2][srow] = f2tf(vv.z);
                Vt[ch + i * 4 + 3][srow] = f2tf(vv.w);
            }
        }
        __syncthreads();

        // ---- S = Q @ K^T (ldmatrix B-frags, x4 covers two k8 steps) ----
        float s[8][4] = {};
        #pragma unroll
        for (int kp2 = 0; kp2 < 4; kp2++) {
            #pragma unroll
            for (int j = 0; j < 8; j++) {
                uint32_t b0, b1, b2, b3;
                ldsm4(b0, b1, b2, b3,
                      ksBase + ((j * 8) * APAD + kp2 * 16) * 4 + offB);
                mma_tf32(s[j], qa[2 * kp2],     b0, b1);
                mma_tf32(s[j], qa[2 * kp2 + 1], b2, b3);
            }
        }

        // ---- causal mask (diagonal tile) ----
        if (kt == qt) {
            #pragma unroll
            for (int j = 0; j < 8; j++) {
                const int c0 = kt * 64 + j * 8 + 2 * (lane & 3);
                if (c0     > gr0) s[j][0] = -1e30f;
                if (c0 + 1 > gr0) s[j][1] = -1e30f;
                if (c0     > gr1) s[j][2] = -1e30f;
                if (c0 + 1 > gr1) s[j][3] = -1e30f;
            }
        }

        // ---- online softmax (base-2, register-resident) ----
        float mx0 = -1e30f, mx1 = -1e30f;
        #pragma unroll
        for (int j = 0; j < 8; j++) {
            mx0 = fmaxf(mx0, fmaxf(s[j][0], s[j][1]));
            mx1 = fmaxf(mx1, fmaxf(s[j][2], s[j][3]));
        }
        mx0 = fmaxf(mx0, __shfl_xor_sync(0xffffffff, mx0, 1));
        mx0 = fmaxf(mx0, __shfl_xor_sync(0xffffffff, mx0, 2));
        mx1 = fmaxf(mx1, __shfl_xor_sync(0xffffffff, mx1, 1));
        mx1 = fmaxf(mx1, __shfl_xor_sync(0xffffffff, mx1, 2));

        const float nm0 = fmaxf(mrow0, mx0);
        const float nm1 = fmaxf(mrow1, mx1);
        const float corr0 = ex2(mrow0 - nm0);
        const float corr1 = ex2(mrow1 - nm1);
        mrow0 = nm0; mrow1 = nm1;

        float sum0 = 0.0f, sum1 = 0.0f;
        #pragma unroll
        for (int j = 0; j < 8; j++) {
            s[j][0] = ex2(s[j][0] - nm0); sum0 += s[j][0];
            s[j][1] = ex2(s[j][1] - nm0); sum0 += s[j][1];
            s[j][2] = ex2(s[j][2] - nm1); sum1 += s[j][2];
            s[j][3] = ex2(s[j][3] - nm1); sum1 += s[j][3];
        }
        sum0 += __shfl_xor_sync(0xffffffff, sum0, 1);
        sum0 += __shfl_xor_sync(0xffffffff, sum0, 2);
        sum1 += __shfl_xor_sync(0xffffffff, sum1, 1);
        sum1 += __shfl_xor_sync(0xffffffff, sum1, 2);
        l0 = l0 * corr0 + sum0;
        l1 = l1 * corr1 + sum1;

        #pragma unroll
        for (int j = 0; j < 8; j++) {
            oa[j][0] *= corr0; oa[j][1] *= corr0;
            oa[j][2] *= corr1; oa[j][3] *= corr1;
        }

        // ---- store P (vectorized, warp-private rows) ----
        {
            const int r = warp * 16 + (lane >> 2);
            #pragma unroll
            for (int j = 0; j < 8; j++) {
                const int c = j * 8 + 2 * (lane & 3);
                uint2 u0 = { f2tf(s[j][0]), f2tf(s[j][1]) };
                uint2 u1 = { f2tf(s[j][2]), f2tf(s[j][3]) };
                *(uint2*)&Ps[r][c]     = u0;
                *(uint2*)&Ps[r + 8][c] = u1;
            }
        }
        __syncwarp();

        // ---- O += P @ V  (P frags via ldmatrix, V frags from Vt) ----
        uint32_t af[8][4];
        #pragma unroll
        for (int k2 = 0; k2 < 8; k2++) {
            ldsm4(af[k2][0], af[k2][1], af[k2][2], af[k2][3],
                  psBase + ((warp * 16) * APAD + k2 * 8) * 4 + offA);
        }
        #pragma unroll
        for (int kp2 = 0; kp2 < 4; kp2++) {
            #pragma unroll
            for (int j = 0; j < 8; j++) {
                uint32_t b0, b1, b2, b3;
                ldsm4(b0, b1, b2, b3,
                      vtBase + ((j * 8) * APAD + kp2 * 16) * 4 + offB);
                mma_tf32(oa[j], af[2 * kp2],     b0, b1);
                mma_tf32(oa[j], af[2 * kp2 + 1], b2, b3);
            }
        }
    }

    // ---- epilogue: normalize, write [B,T,C] ----
    const float inv0 = 1.0f / l0;
    const float inv1 = 1.0f / l1;
    const int bq = bh >> 4;
    const int h  = bh & 15;
    const int trow = qt * 64 + warp * 16 + (lane >> 2);
    #pragma unroll
    for (int j = 0; j < 8; j++) {
        const int d = j * 8 + 2 * (lane & 3);
        float2 v0 = { oa[j][0] * inv0, oa[j][1] * inv0 };
        float2 v1 = { oa[j][2] * inv1, oa[j][3] * inv1 };
        *(float2*)(out + (size_t)(bq * T_DIM + trow) * C_DIM + h * HD + d)     = v0;
        *(float2*)(out + (size_t)(bq * T_DIM + trow + 8) * C_DIM + h * HD + d) = v1;
    }
}

// ---------------------------------------------------------------------------
extern "C" void kernel_launch(void* const* d_in, const int* in_sizes, int n_in,
                              void* d_out, int out_size)
{
    const float* x = (const float*)d_in[0];   // [4, 2048, 1024]
    const float* W = (const float*)d_in[1];   // [3072, 1024]
    const float* b = (const float*)d_in[2];   // [3072]
    float* out = (float*)d_out;               // [4, 2048, 1024]

    cudaFuncSetAttribute(attn_tf32, cudaFuncAttributeMaxDynamicSharedMemorySize,
                         ATTN_SMEM_BYTES);

    qkv_gemm_tf32<<<dim3(N_TOT / 128, M_TOT / 128), 256>>>(x, W, b);
    attn_tf32<<<dim3(T_DIM / 64, B_DIM * H_DIM), 128, ATTN_SMEM_BYTES>>>(out);
}

// round 8
// speedup vs baseline: 1.3006x; 1.1566x over previous
#include <cuda_runtime.h>
#include <cstdint>

#define C_DIM 1024
#define B_DIM 4
#define T_DIM 2048
#define H_DIM 16
#define HD    64
#define M_TOT (B_DIM * T_DIM)   // 8192
#define N_TOT (3 * C_DIM)       // 3072

// Q/K in [B,H,T,D]; V stored TRANSPOSED in [B,H,D,T]
__device__ float g_q[(size_t)M_TOT * C_DIM];
__device__ float g_k[(size_t)M_TOT * C_DIM];
__device__ float g_v[(size_t)M_TOT * C_DIM];

__device__ __forceinline__ uint32_t f2tf(float f) {
    uint32_t u;
    asm("cvt.rna.tf32.f32 %0, %1;" : "=r"(u) : "f"(f));
    return u;
}

__device__ __forceinline__ float ex2(float x) {
    float y;
    asm("ex2.approx.f32 %0, %1;" : "=f"(y) : "f"(x));
    return y;
}

__device__ __forceinline__ void mma_tf32(float c[4], const uint32_t a[4],
                                         uint32_t b0, uint32_t b1) {
    asm volatile(
        "mma.sync.aligned.m16n8k8.row.col.f32.tf32.tf32.f32 "
        "{%0,%1,%2,%3}, {%4,%5,%6,%7}, {%8,%9}, {%0,%1,%2,%3};"
        : "+f"(c[0]), "+f"(c[1]), "+f"(c[2]), "+f"(c[3])
        : "r"(a[0]), "r"(a[1]), "r"(a[2]), "r"(a[3]), "r"(b0), "r"(b1));
}

__device__ __forceinline__ void ldsm4(uint32_t& d0, uint32_t& d1,
                                      uint32_t& d2, uint32_t& d3,
                                      uint32_t addr) {
    asm volatile("ldmatrix.sync.aligned.m8n8.x4.shared.b16 {%0,%1,%2,%3}, [%4];"
                 : "=r"(d0), "=r"(d1), "=r"(d2), "=r"(d3) : "r"(addr));
}

__device__ __forceinline__ uint32_t smem_u32(const void* p) {
    uint32_t a;
    asm("{ .reg .u64 t; cvta.to.shared.u64 t, %1; cvt.u32.u64 %0, t; }"
        : "=r"(a) : "l"(p));
    return a;
}

// ---------------------------------------------------------------------------
// QKV GEMM (TF32 mma.sync + ldmatrix). CTA 128x128, k16, 8 warps (2Mx4N).
// Q/K scattered to [B,H,T,D]; V scattered TRANSPOSED to [B,H,D,T].
// ---------------------------------------------------------------------------
#define GPAD 20

__global__ __launch_bounds__(256) void qkv_gemm_tf32(
    const float* __restrict__ x,
    const float* __restrict__ W,
    const float* __restrict__ b)
{
    __shared__ uint32_t As[128][GPAD];
    __shared__ uint32_t Bs[128][GPAD];

    const int tid  = threadIdx.x;
    const int lane = tid & 31;
    const int warp = tid >> 5;
    const int wm = warp >> 2;
    const int wn = warp & 3;
    const int m0 = blockIdx.y * 128;
    const int n0 = blockIdx.x * 128;

    const uint32_t aBase = smem_u32(As);
    const uint32_t bBase = smem_u32(Bs);

    const uint32_t offA = ((((lane & 7) + ((lane >> 3) & 1) * 8) * GPAD)
                           + (lane >> 4) * 4) * 4;
    const uint32_t offBP = ((((lane & 7) + (lane >> 4) * 8) * GPAD)
                            + ((lane >> 3) & 1) * 4) * 4;

    const int lrow = tid >> 1;
    const int lcol = (tid & 1) * 8;
    const float* ap = x + (size_t)(m0 + lrow) * C_DIM + lcol;
    const float* bp = W + (size_t)(n0 + lrow) * C_DIM + lcol;

    float acc[4][4][4] = {};

    for (int k0 = 0; k0 < C_DIM; k0 += 16) {
        float4 av0 = *(const float4*)(ap + k0);
        float4 av1 = *(const float4*)(ap + k0 + 4);
        float4 bv0 = *(const float4*)(bp + k0);
        float4 bv1 = *(const float4*)(bp + k0 + 4);
        __syncthreads();
        {
            uint4 v;
            v.x = f2tf(av0.x); v.y = f2tf(av0.y); v.z = f2tf(av0.z); v.w = f2tf(av0.w);
            *(uint4*)&As[lrow][lcol] = v;
            v.x = f2tf(av1.x); v.y = f2tf(av1.y); v.z = f2tf(av1.z); v.w = f2tf(av1.w);
            *(uint4*)&As[lrow][lcol + 4] = v;
            v.x = f2tf(bv0.x); v.y = f2tf(bv0.y); v.z = f2tf(bv0.z); v.w = f2tf(bv0.w);
            *(uint4*)&Bs[lrow][lcol] = v;
            v.x = f2tf(bv1.x); v.y = f2tf(bv1.y); v.z = f2tf(bv1.z); v.w = f2tf(bv1.w);
            *(uint4*)&Bs[lrow][lcol + 4] = v;
        }
        __syncthreads();

        #pragma unroll
        for (int ks = 0; ks < 16; ks += 8) {
            uint32_t af[4][4];
            #pragma unroll
            for (int mt = 0; mt < 4; mt++) {
                ldsm4(af[mt][0], af[mt][1], af[mt][2], af[mt][3],
                      aBase + ((wm * 64 + mt * 16) * GPAD + ks) * 4 + offA);
            }
            uint32_t bf[4][2];
            ldsm4(bf[0][0], bf[0][1], bf[1][0], bf[1][1],
                  bBase + ((wn * 32) * GPAD + ks) * 4 + offBP);
            ldsm4(bf[2][0], bf[2][1], bf[3][0], bf[3][1],
                  bBase + ((wn * 32 + 16) * GPAD + ks) * 4 + offBP);
            #pragma unroll
            for (int mt = 0; mt < 4; mt++)
                #pragma unroll
                for (int nt = 0; nt < 4; nt++)
                    mma_tf32(acc[mt][nt], af[mt], bf[nt][0], bf[nt][1]);
        }
    }

    const int which = n0 >> 10;
    const int bq = m0 >> 11;
    const int t0 = m0 & (T_DIM - 1);
    const int h  = (((n0 & 1023) + wn * 32) >> 6);

    if (which < 2) {
        float* dst = (which == 0) ? g_q : g_k;
        #pragma unroll
        for (int nt = 0; nt < 4; nt++) {
            const int ncol = wn * 32 + nt * 8 + 2 * (lane & 3);
            const float2 bias = *(const float2*)(b + n0 + ncol);
            const int d = ncol & 63;
            const size_t rowbase = (size_t)(bq * H_DIM + h) * T_DIM;
            #pragma unroll
            for (int mt = 0; mt < 4; mt++) {
                const int t = t0 + wm * 64 + mt * 16 + (lane >> 2);
                float2 v0 = { acc[mt][nt][0] + bias.x, acc[mt][nt][1] + bias.y };
                float2 v1 = { acc[mt][nt][2] + bias.x, acc[mt][nt][3] + bias.y };
                *(float2*)(dst + (rowbase + t) * HD + d)       = v0;
                *(float2*)(dst + (rowbase + t + 8) * HD + d)   = v1;
            }
        }
    } else {
        // V: transposed scatter to [B,H,D,T]
        const size_t hb = (size_t)(bq * H_DIM + h) * HD;
        #pragma unroll
        for (int nt = 0; nt < 4; nt++) {
            const int ncol = wn * 32 + nt * 8 + 2 * (lane & 3);
            const float2 bias = *(const float2*)(b + n0 + ncol);
            const int d = ncol & 63;
            float* r0 = g_v + (hb + d)     * T_DIM;
            float* r1 = g_v + (hb + d + 1) * T_DIM;
            #pragma unroll
            for (int mt = 0; mt < 4; mt++) {
                const int t = t0 + wm * 64 + mt * 16 + (lane >> 2);
                r0[t]     = acc[mt][nt][0] + bias.x;
                r1[t]     = acc[mt][nt][1] + bias.y;
                r0[t + 8] = acc[mt][nt][2] + bias.x;
                r1[t + 8] = acc[mt][nt][3] + bias.y;
            }
        }
    }
}

// ---------------------------------------------------------------------------
// Flash attention: CTA = 128 q-rows, 4 warps x 32 rows (2 m16 tiles/warp).
// KV tiles of 64. K row-major smem; V staged from pre-transposed gmem.
// smem: Ks[64][68], Vt[64][68], Ps[128][68] (Q staged via Ps, warp-local).
// ---------------------------------------------------------------------------
#define APAD 68
#define SMEM_U32 ((64 + 64 + 128) * APAD)
#define ATTN_SMEM_BYTES (SMEM_U32 * 4)
#define QSCALE 0.1803368801111204f   // (1/8) * log2(e)

__global__ __launch_bounds__(128, 2) void attn_tf32(float* __restrict__ out)
{
    extern __shared__ uint32_t sm[];
    uint32_t (*Ks)[APAD] = (uint32_t(*)[APAD])(sm);
    uint32_t (*Vt)[APAD] = (uint32_t(*)[APAD])(sm + 64 * APAD);
    uint32_t (*Ps)[APAD] = (uint32_t(*)[APAD])(sm + 2 * 64 * APAD);

    const int tid  = threadIdx.x;
    const int lane = tid & 31;
    const int warp = tid >> 5;
    const int qt = (gridDim.x - 1) - blockIdx.x;   // heavy tiles first
    const int bh = blockIdx.y;

    const uint32_t ksBase = smem_u32(Ks);
    const uint32_t vtBase = smem_u32(Vt);
    const uint32_t psBase = smem_u32(Ps);

    const uint32_t offA = ((((lane & 7) + ((lane >> 3) & 1) * 8) * APAD)
                           + (lane >> 4) * 4) * 4;
    const uint32_t offB = (((lane & 7) * APAD) + (lane >> 3) * 4) * 4;

    const float* Qg  = g_q + (size_t)bh * T_DIM * HD;
    const float* Kg  = g_k + (size_t)bh * T_DIM * HD;
    const float* Vgt = g_v + (size_t)bh * HD * T_DIM;

    // ---- stage Q (warp-local rows), pull qa fragments ----
    {
        const float* qp = Qg + (size_t)(qt * 128 + tid) * HD;
        #pragma unroll
        for (int i = 0; i < 16; i++) {
            float4 v = *(const float4*)(qp + i * 4);
            uint4 u;
            u.x = f2tf(v.x * QSCALE); u.y = f2tf(v.y * QSCALE);
            u.z = f2tf(v.z * QSCALE); u.w = f2tf(v.w * QSCALE);
            *(uint4*)&Ps[tid][i * 4] = u;
        }
    }
    __syncwarp();
    uint32_t qa[2][8][4];
    #pragma unroll
    for (int mt = 0; mt < 2; mt++)
        #pragma unroll
        for (int k = 0; k < 8; k++)
            ldsm4(qa[mt][k][0], qa[mt][k][1], qa[mt][k][2], qa[mt][k][3],
                  psBase + ((warp * 32 + mt * 16) * APAD + k * 8) * 4 + offA);
    __syncwarp();

    float oa[2][8][4] = {};
    float mr[2][2] = {{-1e30f, -1e30f}, {-1e30f, -1e30f}};
    float lv[2][2] = {};
    const int rbase = qt * 128 + warp * 32;
    const int NKV = 2 * qt + 2;

    const int srow = tid >> 1;           // 0..63
    const int ch   = (tid & 1) * 32;     // 0 or 32

    for (int kt = 0; kt < NKV; kt++) {
        if (kt) __syncthreads();
        // ---- stage K (row-major) and Vt (row-major from [B,H,D,T]) ----
        {
            const float* kp = Kg  + (size_t)(kt * 64 + srow) * HD + ch;
            const float* vp = Vgt + (size_t)srow * T_DIM + kt * 64 + ch;
            #pragma unroll
            for (int i = 0; i < 8; i++) {
                float4 kv = *(const float4*)(kp + i * 4);
                uint4 u;
                u.x = f2tf(kv.x); u.y = f2tf(kv.y);
                u.z = f2tf(kv.z); u.w = f2tf(kv.w);
                *(uint4*)&Ks[srow][ch + i * 4] = u;
                float4 vv = *(const float4*)(vp + i * 4);
                u.x = f2tf(vv.x); u.y = f2tf(vv.y);
                u.z = f2tf(vv.z); u.w = f2tf(vv.w);
                *(uint4*)&Vt[srow][ch + i * 4] = u;
            }
        }
        __syncthreads();

        // skip fully-masked tiles for this warp
        if (kt * 64 > rbase + 31) continue;

        // ---- S = Q @ K^T ----
        float s[2][8][4] = {};
        #pragma unroll
        for (int kp2 = 0; kp2 < 4; kp2++) {
            #pragma unroll
            for (int j = 0; j < 8; j++) {
                uint32_t b0, b1, b2, b3;
                ldsm4(b0, b1, b2, b3,
                      ksBase + ((j * 8) * APAD + kp2 * 16) * 4 + offB);
                mma_tf32(s[0][j], qa[0][2 * kp2],     b0, b1);
                mma_tf32(s[0][j], qa[0][2 * kp2 + 1], b2, b3);
                mma_tf32(s[1][j], qa[1][2 * kp2],     b0, b1);
                mma_tf32(s[1][j], qa[1][2 * kp2 + 1], b2, b3);
            }
        }

        // ---- causal mask (only tiles overlapping the diagonal) ----
        if (kt * 64 + 63 > rbase) {
            #pragma unroll
            for (int mt = 0; mt < 2; mt++) {
                const int gr0 = rbase + mt * 16 + (lane >> 2);
                const int gr1 = gr0 + 8;
                #pragma unroll
                for (int j = 0; j < 8; j++) {
                    const int c0 = kt * 64 + j * 8 + 2 * (lane & 3);
                    if (c0     > gr0) s[mt][j][0] = -1e30f;
                    if (c0 + 1 > gr0) s[mt][j][1] = -1e30f;
                    if (c0     > gr1) s[mt][j][2] = -1e30f;
                    if (c0 + 1 > gr1) s[mt][j][3] = -1e30f;
                }
            }
        }

        // ---- online softmax (base-2) per m-tile ----
        #pragma unroll
        for (int mt = 0; mt < 2; mt++) {
            float mx0 = -1e30f, mx1 = -1e30f;
            #pragma unroll
            for (int j = 0; j < 8; j++) {
                mx0 = fmaxf(mx0, fmaxf(s[mt][j][0], s[mt][j][1]));
                mx1 = fmaxf(mx1, fmaxf(s[mt][j][2], s[mt][j][3]));
            }
            mx0 = fmaxf(mx0, __shfl_xor_sync(0xffffffff, mx0, 1));
            mx0 = fmaxf(mx0, __shfl_xor_sync(0xffffffff, mx0, 2));
            mx1 = fmaxf(mx1, __shfl_xor_sync(0xffffffff, mx1, 1));
            mx1 = fmaxf(mx1, __shfl_xor_sync(0xffffffff, mx1, 2));

            const float nm0 = fmaxf(mr[mt][0], mx0);
            const float nm1 = fmaxf(mr[mt][1], mx1);
            const float corr0 = ex2(mr[mt][0] - nm0);
            const float corr1 = ex2(mr[mt][1] - nm1);
            mr[mt][0] = nm0; mr[mt][1] = nm1;

            float sum0 = 0.0f, sum1 = 0.0f;
            #pragma unroll
            for (int j = 0; j < 8; j++) {
                s[mt][j][0] = ex2(s[mt][j][0] - nm0); sum0 += s[mt][j][0];
                s[mt][j][1] = ex2(s[mt][j][1] - nm0); sum0 += s[mt][j][1];
                s[mt][j][2] = ex2(s[mt][j][2] - nm1); sum1 += s[mt][j][2];
                s[mt][j][3] = ex2(s[mt][j][3] - nm1); sum1 += s[mt][j][3];
            }
            sum0 += __shfl_xor_sync(0xffffffff, sum0, 1);
            sum0 += __shfl_xor_sync(0xffffffff, sum0, 2);
            sum1 += __shfl_xor_sync(0xffffffff, sum1, 1);
            sum1 += __shfl_xor_sync(0xffffffff, sum1, 2);
            lv[mt][0] = lv[mt][0] * corr0 + sum0;
            lv[mt][1] = lv[mt][1] * corr1 + sum1;

            #pragma unroll
            for (int j = 0; j < 8; j++) {
                oa[mt][j][0] *= corr0; oa[mt][j][1] *= corr0;
                oa[mt][j][2] *= corr1; oa[mt][j][3] *= corr1;
            }

            // store P (warp-private rows)
            const int r = warp * 32 + mt * 16 + (lane >> 2);
            #pragma unroll
            for (int j = 0; j < 8; j++) {
                const int c = j * 8 + 2 * (lane & 3);
                uint2 u0 = { f2tf(s[mt][j][0]), f2tf(s[mt][j][1]) };
                uint2 u1 = { f2tf(s[mt][j][2]), f2tf(s[mt][j][3]) };
                *(uint2*)&Ps[r][c]     = u0;
                *(uint2*)&Ps[r + 8][c] = u1;
            }
        }
        __syncwarp();

        // ---- O += P @ V ----
        #pragma unroll
        for (int kp2 = 0; kp2 < 4; kp2++) {
            uint32_t a0[4], a1[4], a2[4], a3[4];
            ldsm4(a0[0], a0[1], a0[2], a0[3],
                  psBase + ((warp * 32) * APAD + kp2 * 16) * 4 + offA);
            ldsm4(a1[0], a1[1], a1[2], a1[3],
                  psBase + ((warp * 32) * APAD + kp2 * 16 + 8) * 4 + offA);
            ldsm4(a2[0], a2[1], a2[2], a2[3],
                  psBase + ((warp * 32 + 16) * APAD + kp2 * 16) * 4 + offA);
            ldsm4(a3[0], a3[1], a3[2], a3[3],
                  psBase + ((warp * 32 + 16) * APAD + kp2 * 16 + 8) * 4 + offA);
            #pragma unroll
            for (int j = 0; j < 8; j++) {
                uint32_t b0, b1, b2, b3;
                ldsm4(b0, b1, b2, b3,
                      vtBase + ((j * 8) * APAD + kp2 * 16) * 4 + offB);
                mma_tf32(oa[0][j], a0, b0, b1);
                mma_tf32(oa[0][j], a1, b2, b3);
                mma_tf32(oa[1][j], a2, b0, b1);
                mma_tf32(oa[1][j], a3, b2, b3);
            }
        }
    }

    // ---- epilogue: normalize, write [B,T,C] ----
    const int bq = bh >> 4;
    const int h  = bh & 15;
    #pragma unroll
    for (int mt = 0; mt < 2; mt++) {
        const float inv0 = 1.0f / lv[mt][0];
        const float inv1 = 1.0f / lv[mt][1];
        const int trow = rbase + mt * 16 + (lane >> 2);
        #pragma unroll
        for (int j = 0; j < 8; j++) {
            const int d = j * 8 + 2 * (lane & 3);
            float2 v0 = { oa[mt][j][0] * inv0, oa[mt][j][1] * inv0 };
            float2 v1 = { oa[mt][j][2] * inv1, oa[mt][j][3] * inv1 };
            *(float2*)(out + (size_t)(bq * T_DIM + trow) * C_DIM + h * HD + d)     = v0;
            *(float2*)(out + (size_t)(bq * T_DIM + trow + 8) * C_DIM + h * HD + d) = v1;
        }
    }
}

// ---------------------------------------------------------------------------
extern "C" void kernel_launch(void* const* d_in, const int* in_sizes, int n_in,
                              void* d_out, int out_size)
{
    const float* x = (const float*)d_in[0];   // [4, 2048, 1024]
    const float* W = (const float*)d_in[1];   // [3072, 1024]
    const float* b = (const float*)d_in[2];   // [3072]
    float* out = (float*)d_out;               // [4, 2048, 1024]

    cudaFuncSetAttribute(attn_tf32, cudaFuncAttributeMaxDynamicSharedMemorySize,
                         ATTN_SMEM_BYTES);

    qkv_gemm_tf32<<<dim3(N_TOT / 128, M_TOT / 128), 256>>>(x, W, b);
    attn_tf32<<<dim3(T_DIM / 128, B_DIM * H_DIM), 128, ATTN_SMEM_BYTES>>>(out);
}

// round 9
// speedup vs baseline: 1.3741x; 1.0565x over previous
#include <cuda_runtime.h>
#include <cstdint>

#define C_DIM 1024
#define B_DIM 4
#define T_DIM 2048
#define H_DIM 16
#define HD    64
#define M_TOT (B_DIM * T_DIM)   // 8192
#define N_TOT (3 * C_DIM)       // 3072

// Q/K in [B,H,T,D]; V stored TRANSPOSED in [B,H,D,T]
__device__ float g_q[(size_t)M_TOT * C_DIM];
__device__ float g_k[(size_t)M_TOT * C_DIM];
__device__ float g_v[(size_t)M_TOT * C_DIM];

__device__ __forceinline__ uint32_t f2tf(float f) {
    uint32_t u;
    asm("cvt.rna.tf32.f32 %0, %1;" : "=r"(u) : "f"(f));
    return u;
}

__device__ __forceinline__ float ex2(float x) {
    float y;
    asm("ex2.approx.f32 %0, %1;" : "=f"(y) : "f"(x));
    return y;
}

__device__ __forceinline__ void mma_tf32(float c[4], const uint32_t a[4],
                                         uint32_t b0, uint32_t b1) {
    asm volatile(
        "mma.sync.aligned.m16n8k8.row.col.f32.tf32.tf32.f32 "
        "{%0,%1,%2,%3}, {%4,%5,%6,%7}, {%8,%9}, {%0,%1,%2,%3};"
        : "+f"(c[0]), "+f"(c[1]), "+f"(c[2]), "+f"(c[3])
        : "r"(a[0]), "r"(a[1]), "r"(a[2]), "r"(a[3]), "r"(b0), "r"(b1));
}

__device__ __forceinline__ void ldsm4(uint32_t& d0, uint32_t& d1,
                                      uint32_t& d2, uint32_t& d3,
                                      uint32_t addr) {
    asm volatile("ldmatrix.sync.aligned.m8n8.x4.shared.b16 {%0,%1,%2,%3}, [%4];"
                 : "=r"(d0), "=r"(d1), "=r"(d2), "=r"(d3) : "r"(addr));
}

__device__ __forceinline__ uint32_t smem_u32(const void* p) {
    uint32_t a;
    asm("{ .reg .u64 t; cvta.to.shared.u64 t, %1; cvt.u32.u64 %0, t; }"
        : "=r"(a) : "l"(p));
    return a;
}

// ---------------------------------------------------------------------------
// QKV GEMM (TF32 mma.sync + ldmatrix), SOFTWARE-PIPELINED:
// double-buffered smem (dynamic), register prefetch, ONE sync per k-tile.
// CTA 128x128, k16, 8 warps (2Mx4N), warp tile 64x32.
// Q/K scattered to [B,H,T,D]; V scattered TRANSPOSED to [B,H,D,T].
// ---------------------------------------------------------------------------
#define GPAD 20
#define GEMM_STAGE_U32 (128 * GPAD)
#define GEMM_SMEM_BYTES (4 * GEMM_STAGE_U32 * 4)   // As[2] + Bs[2] = 81920 B

__global__ __launch_bounds__(256, 2) void qkv_gemm_tf32(
    const float* __restrict__ x,
    const float* __restrict__ W,
    const float* __restrict__ b)
{
    extern __shared__ uint32_t gsm[];
    // layout: As[2][128][GPAD] then Bs[2][128][GPAD]
    uint32_t* Abuf = gsm;
    uint32_t* Bbuf = gsm + 2 * GEMM_STAGE_U32;

    const int tid  = threadIdx.x;
    const int lane = tid & 31;
    const int warp = tid >> 5;
    const int wm = warp >> 2;
    const int wn = warp & 3;
    const int m0 = blockIdx.y * 128;
    const int n0 = blockIdx.x * 128;

    const uint32_t aBase = smem_u32(Abuf);
    const uint32_t bBase = smem_u32(Bbuf);

    const uint32_t offA = ((((lane & 7) + ((lane >> 3) & 1) * 8) * GPAD)
                           + (lane >> 4) * 4) * 4;
    const uint32_t offBP = ((((lane & 7) + (lane >> 4) * 8) * GPAD)
                            + ((lane >> 3) & 1) * 4) * 4;

    const int lrow = tid >> 1;
    const int lcol = (tid & 1) * 8;
    const float* ap = x + (size_t)(m0 + lrow) * C_DIM + lcol;
    const float* bp = W + (size_t)(n0 + lrow) * C_DIM + lcol;

    float acc[4][4][4] = {};

    // prologue: load k-tile 0, stage into buffer 0
    float4 av0 = *(const float4*)(ap);
    float4 av1 = *(const float4*)(ap + 4);
    float4 bv0 = *(const float4*)(bp);
    float4 bv1 = *(const float4*)(bp + 4);
    {
        uint32_t* A0 = Abuf + lrow * GPAD + lcol;
        uint32_t* B0 = Bbuf + lrow * GPAD + lcol;
        uint4 v;
        v.x = f2tf(av0.x); v.y = f2tf(av0.y); v.z = f2tf(av0.z); v.w = f2tf(av0.w);
        *(uint4*)A0 = v;
        v.x = f2tf(av1.x); v.y = f2tf(av1.y); v.z = f2tf(av1.z); v.w = f2tf(av1.w);
        *(uint4*)(A0 + 4) = v;
        v.x = f2tf(bv0.x); v.y = f2tf(bv0.y); v.z = f2tf(bv0.z); v.w = f2tf(bv0.w);
        *(uint4*)B0 = v;
        v.x = f2tf(bv1.x); v.y = f2tf(bv1.y); v.z = f2tf(bv1.z); v.w = f2tf(bv1.w);
        *(uint4*)(B0 + 4) = v;
    }
    __syncthreads();

    #pragma unroll 1
    for (int kt = 0; kt < 64; kt++) {
        const int st = kt & 1;
        const uint32_t soff = (uint32_t)st * (GEMM_STAGE_U32 * 4);  // bytes

        // issue next k-tile's global loads (consumed after compute)
        if (kt < 63) {
            const float* apn = ap + (kt + 1) * 16;
            const float* bpn = bp + (kt + 1) * 16;
            av0 = *(const float4*)(apn);
            av1 = *(const float4*)(apn + 4);
            bv0 = *(const float4*)(bpn);
            bv1 = *(const float4*)(bpn + 4);
        }

        // compute on stage st
        #pragma unroll
        for (int ks = 0; ks < 16; ks += 8) {
            uint32_t af[4][4];
            #pragma unroll
            for (int mt = 0; mt < 4; mt++) {
                ldsm4(af[mt][0], af[mt][1], af[mt][2], af[mt][3],
                      aBase + soff + ((wm * 64 + mt * 16) * GPAD + ks) * 4 + offA);
            }
            uint32_t bf[4][2];
            ldsm4(bf[0][0], bf[0][1], bf[1][0], bf[1][1],
                  bBase + soff + ((wn * 32) * GPAD + ks) * 4 + offBP);
            ldsm4(bf[2][0], bf[2][1], bf[3][0], bf[3][1],
                  bBase + soff + ((wn * 32 + 16) * GPAD + ks) * 4 + offBP);
            #pragma unroll
            for (int mt = 0; mt < 4; mt++)
                #pragma unroll
                for (int nt = 0; nt < 4; nt++)
                    mma_tf32(acc[mt][nt], af[mt], bf[nt][0], bf[nt][1]);
        }

        // stage next k-tile into the other buffer, then ONE sync
        if (kt < 63) {
            uint32_t* An = Abuf + (st ^ 1) * GEMM_STAGE_U32 + lrow * GPAD + lcol;
            uint32_t* Bn = Bbuf + (st ^ 1) * GEMM_STAGE_U32 + lrow * GPAD + lcol;
            uint4 v;
            v.x = f2tf(av0.x); v.y = f2tf(av0.y); v.z = f2tf(av0.z); v.w = f2tf(av0.w);
            *(uint4*)An = v;
            v.x = f2tf(av1.x); v.y = f2tf(av1.y); v.z = f2tf(av1.z); v.w = f2tf(av1.w);
            *(uint4*)(An + 4) = v;
            v.x = f2tf(bv0.x); v.y = f2tf(bv0.y); v.z = f2tf(bv0.z); v.w = f2tf(bv0.w);
            *(uint4*)Bn = v;
            v.x = f2tf(bv1.x); v.y = f2tf(bv1.y); v.z = f2tf(bv1.z); v.w = f2tf(bv1.w);
            *(uint4*)(Bn + 4) = v;
            __syncthreads();
        }
    }

    const int which = n0 >> 10;
    const int bq = m0 >> 11;
    const int t0 = m0 & (T_DIM - 1);
    const int h  = (((n0 & 1023) + wn * 32) >> 6);

    if (which < 2) {
        float* dst = (which == 0) ? g_q : g_k;
        #pragma unroll
        for (int nt = 0; nt < 4; nt++) {
            const int ncol = wn * 32 + nt * 8 + 2 * (lane & 3);
            const float2 bias = *(const float2*)(b + n0 + ncol);
            const int d = ncol & 63;
            const size_t rowbase = (size_t)(bq * H_DIM + h) * T_DIM;
            #pragma unroll
            for (int mt = 0; mt < 4; mt++) {
                const int t = t0 + wm * 64 + mt * 16 + (lane >> 2);
                float2 v0 = { acc[mt][nt][0] + bias.x, acc[mt][nt][1] + bias.y };
                float2 v1 = { acc[mt][nt][2] + bias.x, acc[mt][nt][3] + bias.y };
                *(float2*)(dst + (rowbase + t) * HD + d)       = v0;
                *(float2*)(dst + (rowbase + t + 8) * HD + d)   = v1;
            }
        }
    } else {
        // V: transposed scatter to [B,H,D,T]
        const size_t hb = (size_t)(bq * H_DIM + h) * HD;
        #pragma unroll
        for (int nt = 0; nt < 4; nt++) {
            const int ncol = wn * 32 + nt * 8 + 2 * (lane & 3);
            const float2 bias = *(const float2*)(b + n0 + ncol);
            const int d = ncol & 63;
            float* r0 = g_v + (hb + d)     * T_DIM;
            float* r1 = g_v + (hb + d + 1) * T_DIM;
            #pragma unroll
            for (int mt = 0; mt < 4; mt++) {
                const int t = t0 + wm * 64 + mt * 16 + (lane >> 2);
                r0[t]     = acc[mt][nt][0] + bias.x;
                r1[t]     = acc[mt][nt][1] + bias.y;
                r0[t + 8] = acc[mt][nt][2] + bias.x;
                r1[t + 8] = acc[mt][nt][3] + bias.y;
            }
        }
    }
}

// ---------------------------------------------------------------------------
// Flash attention: CTA = 128 q-rows, 4 warps x 32 rows (2 m16 tiles/warp).
// KV tiles of 64. K row-major smem; V staged from pre-transposed gmem.
// smem: Ks[64][68], Vt[64][68], Ps[128][68] (Q staged via Ps, warp-local).
// (byte-identical to round 8 — known good)
// ---------------------------------------------------------------------------
#define APAD 68
#define SMEM_U32 ((64 + 64 + 128) * APAD)
#define ATTN_SMEM_BYTES (SMEM_U32 * 4)
#define QSCALE 0.1803368801111204f   // (1/8) * log2(e)

__global__ __launch_bounds__(128, 2) void attn_tf32(float* __restrict__ out)
{
    extern __shared__ uint32_t sm[];
    uint32_t (*Ks)[APAD] = (uint32_t(*)[APAD])(sm);
    uint32_t (*Vt)[APAD] = (uint32_t(*)[APAD])(sm + 64 * APAD);
    uint32_t (*Ps)[APAD] = (uint32_t(*)[APAD])(sm + 2 * 64 * APAD);

    const int tid  = threadIdx.x;
    const int lane = tid & 31;
    const int warp = tid >> 5;
    const int qt = (gridDim.x - 1) - blockIdx.x;   // heavy tiles first
    const int bh = blockIdx.y;

    const uint32_t ksBase = smem_u32(Ks);
    const uint32_t vtBase = smem_u32(Vt);
    const uint32_t psBase = smem_u32(Ps);

    const uint32_t offA = ((((lane & 7) + ((lane >> 3) & 1) * 8) * APAD)
                           + (lane >> 4) * 4) * 4;
    const uint32_t offB = (((lane & 7) * APAD) + (lane >> 3) * 4) * 4;

    const float* Qg  = g_q + (size_t)bh * T_DIM * HD;
    const float* Kg  = g_k + (size_t)bh * T_DIM * HD;
    const float* Vgt = g_v + (size_t)bh * HD * T_DIM;

    // ---- stage Q (warp-local rows), pull qa fragments ----
    {
        const float* qp = Qg + (size_t)(qt * 128 + tid) * HD;
        #pragma unroll
        for (int i = 0; i < 16; i++) {
            float4 v = *(const float4*)(qp + i * 4);
            uint4 u;
            u.x = f2tf(v.x * QSCALE); u.y = f2tf(v.y * QSCALE);
            u.z = f2tf(v.z * QSCALE); u.w = f2tf(v.w * QSCALE);
            *(uint4*)&Ps[tid][i * 4] = u;
        }
    }
    __syncwarp();
    uint32_t qa[2][8][4];
    #pragma unroll
    for (int mt = 0; mt < 2; mt++)
        #pragma unroll
        for (int k = 0; k < 8; k++)
            ldsm4(qa[mt][k][0], qa[mt][k][1], qa[mt][k][2], qa[mt][k][3],
                  psBase + ((warp * 32 + mt * 16) * APAD + k * 8) * 4 + offA);
    __syncwarp();

    float oa[2][8][4] = {};
    float mr[2][2] = {{-1e30f, -1e30f}, {-1e30f, -1e30f}};
    float lv[2][2] = {};
    const int rbase = qt * 128 + warp * 32;
    const int NKV = 2 * qt + 2;

    const int srow = tid >> 1;           // 0..63
    const int ch   = (tid & 1) * 32;     // 0 or 32

    for (int kt = 0; kt < NKV; kt++) {
        if (kt) __syncthreads();
        // ---- stage K (row-major) and Vt (row-major from [B,H,D,T]) ----
        {
            const float* kp = Kg  + (size_t)(kt * 64 + srow) * HD + ch;
            const float* vp = Vgt + (size_t)srow * T_DIM + kt * 64 + ch;
            #pragma unroll
            for (int i = 0; i < 8; i++) {
                float4 kv = *(const float4*)(kp + i * 4);
                uint4 u;
                u.x = f2tf(kv.x); u.y = f2tf(kv.y);
                u.z = f2tf(kv.z); u.w = f2tf(kv.w);
                *(uint4*)&Ks[srow][ch + i * 4] = u;
                float4 vv = *(const float4*)(vp + i * 4);
                u.x = f2tf(vv.x); u.y = f2tf(vv.y);
                u.z = f2tf(vv.z); u.w = f2tf(vv.w);
                *(uint4*)&Vt[srow][ch + i * 4] = u;
            }
        }
        __syncthreads();

        // skip fully-masked tiles for this warp
        if (kt * 64 > rbase + 31) continue;

        // ---- S = Q @ K^T ----
        float s[2][8][4] = {};
        #pragma unroll
        for (int kp2 = 0; kp2 < 4; kp2++) {
            #pragma unroll
            for (int j = 0; j < 8; j++) {
                uint32_t b0, b1, b2, b3;
                ldsm4(b0, b1, b2, b3,
                      ksBase + ((j * 8) * APAD + kp2 * 16) * 4 + offB);
                mma_tf32(s[0][j], qa[0][2 * kp2],     b0, b1);
                mma_tf32(s[0][j], qa[0][2 * kp2 + 1], b2, b3);
                mma_tf32(s[1][j], qa[1][2 * kp2],     b0, b1);
                mma_tf32(s[1][j], qa[1][2 * kp2 + 1], b2, b3);
            }
        }

        // ---- causal mask (only tiles overlapping the diagonal) ----
        if (kt * 64 + 63 > rbase) {
            #pragma unroll
            for (int mt = 0; mt < 2; mt++) {
                const int gr0 = rbase + mt * 16 + (lane >> 2);
                const int gr1 = gr0 + 8;
                #pragma unroll
                for (int j = 0; j < 8; j++) {
                    const int c0 = kt * 64 + j * 8 + 2 * (lane & 3);
                    if (c0     > gr0) s[mt][j][0] = -1e30f;
                    if (c0 + 1 > gr0) s[mt][j][1] = -1e30f;
                    if (c0     > gr1) s[mt][j][2] = -1e30f;
                    if (c0 + 1 > gr1) s[mt][j][3] = -1e30f;
                }
            }
        }

        // ---- online softmax (base-2) per m-tile ----
        #pragma unroll
        for (int mt = 0; mt < 2; mt++) {
            float mx0 = -1e30f, mx1 = -1e30f;
            #pragma unroll
            for (int j = 0; j < 8; j++) {
                mx0 = fmaxf(mx0, fmaxf(s[mt][j][0], s[mt][j][1]));
                mx1 = fmaxf(mx1, fmaxf(s[mt][j][2], s[mt][j][3]));
            }
            mx0 = fmaxf(mx0, __shfl_xor_sync(0xffffffff, mx0, 1));
            mx0 = fmaxf(mx0, __shfl_xor_sync(0xffffffff, mx0, 2));
            mx1 = fmaxf(mx1, __shfl_xor_sync(0xffffffff, mx1, 1));
            mx1 = fmaxf(mx1, __shfl_xor_sync(0xffffffff, mx1, 2));

            const float nm0 = fmaxf(mr[mt][0], mx0);
            const float nm1 = fmaxf(mr[mt][1], mx1);
            const float corr0 = ex2(mr[mt][0] - nm0);
            const float corr1 = ex2(mr[mt][1] - nm1);
            mr[mt][0] = nm0; mr[mt][1] = nm1;

            float sum0 = 0.0f, sum1 = 0.0f;
            #pragma unroll
            for (int j = 0; j < 8; j++) {
                s[mt][j][0] = ex2(s[mt][j][0] - nm0); sum0 += s[mt][j][0];
                s[mt][j][1] = ex2(s[mt][j][1] - nm0); sum0 += s[mt][j][1];
                s[mt][j][2] = ex2(s[mt][j][2] - nm1); sum1 += s[mt][j][2];
                s[mt][j][3] = ex2(s[mt][j][3] - nm1); sum1 += s[mt][j][3];
            }
            sum0 += __shfl_xor_sync(0xffffffff, sum0, 1);
            sum0 += __shfl_xor_sync(0xffffffff, sum0, 2);
            sum1 += __shfl_xor_sync(0xffffffff, sum1, 1);
            sum1 += __shfl_xor_sync(0xffffffff, sum1, 2);
            lv[mt][0] = lv[mt][0] * corr0 + sum0;
            lv[mt][1] = lv[mt][1] * corr1 + sum1;

            #pragma unroll
            for (int j = 0; j < 8; j++) {
                oa[mt][j][0] *= corr0; oa[mt][j][1] *= corr0;
                oa[mt][j][2] *= corr1; oa[mt][j][3] *= corr1;
            }

            // store P (warp-private rows)
            const int r = warp * 32 + mt * 16 + (lane >> 2);
            #pragma unroll
            for (int j = 0; j < 8; j++) {
                const int c = j * 8 + 2 * (lane & 3);
                uint2 u0 = { f2tf(s[mt][j][0]), f2tf(s[mt][j][1]) };
                uint2 u1 = { f2tf(s[mt][j][2]), f2tf(s[mt][j][3]) };
                *(uint2*)&Ps[r][c]     = u0;
                *(uint2*)&Ps[r + 8][c] = u1;
            }
        }
        __syncwarp();

        // ---- O += P @ V ----
        #pragma unroll
        for (int kp2 = 0; kp2 < 4; kp2++) {
            uint32_t a0[4], a1[4], a2[4], a3[4];
            ldsm4(a0[0], a0[1], a0[2], a0[3],
                  psBase + ((warp * 32) * APAD + kp2 * 16) * 4 + offA);
            ldsm4(a1[0], a1[1], a1[2], a1[3],
                  psBase + ((warp * 32) * APAD + kp2 * 16 + 8) * 4 + offA);
            ldsm4(a2[0], a2[1], a2[2], a2[3],
                  psBase + ((warp * 32 + 16) * APAD + kp2 * 16) * 4 + offA);
            ldsm4(a3[0], a3[1], a3[2], a3[3],
                  psBase + ((warp * 32 + 16) * APAD + kp2 * 16 + 8) * 4 + offA);
            #pragma unroll
            for (int j = 0; j < 8; j++) {
                uint32_t b0, b1, b2, b3;
                ldsm4(b0, b1, b2, b3,
                      vtBase + ((j * 8) * APAD + kp2 * 16) * 4 + offB);
                mma_tf32(oa[0][j], a0, b0, b1);
                mma_tf32(oa[0][j], a1, b2, b3);
                mma_tf32(oa[1][j], a2, b0, b1);
                mma_tf32(oa[1][j], a3, b2, b3);
            }
        }
    }

    // ---- epilogue: normalize, write [B,T,C] ----
    const int bq = bh >> 4;
    const int h  = bh & 15;
    #pragma unroll
    for (int mt = 0; mt < 2; mt++) {
        const float inv0 = 1.0f / lv[mt][0];
        const float inv1 = 1.0f / lv[mt][1];
        const int trow = rbase + mt * 16 + (lane >> 2);
        #pragma unroll
        for (int j = 0; j < 8; j++) {
            const int d = j * 8 + 2 * (lane & 3);
            float2 v0 = { oa[mt][j][0] * inv0, oa[mt][j][1] * inv0 };
            float2 v1 = { oa[mt][j][2] * inv1, oa[mt][j][3] * inv1 };
            *(float2*)(out + (size_t)(bq * T_DIM + trow) * C_DIM + h * HD + d)     = v0;
            *(float2*)(out + (size_t)(bq * T_DIM + trow + 8) * C_DIM + h * HD + d) = v1;
        }
    }
}

// ---------------------------------------------------------------------------
extern "C" void kernel_launch(void* const* d_in, const int* in_sizes, int n_in,
                              void* d_out, int out_size)
{
    const float* x = (const float*)d_in[0];   // [4, 2048, 1024]
    const float* W = (const float*)d_in[1];   // [3072, 1024]
    const float* b = (const float*)d_in[2];   // [3072]
    float* out = (float*)d_out;               // [4, 2048, 1024]

    cudaFuncSetAttribute(qkv_gemm_tf32, cudaFuncAttributeMaxDynamicSharedMemorySize,
                         GEMM_SMEM_BYTES);
    cudaFuncSetAttribute(attn_tf32, cudaFuncAttributeMaxDynamicSharedMemorySize,
                         ATTN_SMEM_BYTES);

    qkv_gemm_tf32<<<dim3(N_TOT / 128, M_TOT / 128), 256, GEMM_SMEM_BYTES>>>(x, W, b);
    attn_tf32<<<dim3(T_DIM / 128, B_DIM * H_DIM), 128, ATTN_SMEM_BYTES>>>(out);
}

// round 10
// speedup vs baseline: 1.5349x; 1.1170x over previous
#include <cuda_runtime.h>
#include <cstdint>

#define C_DIM 1024
#define B_DIM 4
#define T_DIM 2048
#define H_DIM 16
#define HD    64
#define M_TOT (B_DIM * T_DIM)   // 8192
#define N_TOT (3 * C_DIM)       // 3072

// Q/K in [B,H,T,D]; V TRANSPOSED in [B,H,D,T]. All stored as tf32-rounded fp32 bits.
__device__ float g_q[(size_t)M_TOT * C_DIM];
__device__ float g_k[(size_t)M_TOT * C_DIM];
__device__ float g_v[(size_t)M_TOT * C_DIM];
// tf32-rounded copies of inputs
__device__ float g_xt[(size_t)M_TOT * C_DIM];
__device__ float g_wt[(size_t)N_TOT * C_DIM];

__device__ __forceinline__ uint32_t f2tf(float f) {
    uint32_t u;
    asm("cvt.rna.tf32.f32 %0, %1;" : "=r"(u) : "f"(f));
    return u;
}

__device__ __forceinline__ float ex2(float x) {
    float y;
    asm("ex2.approx.f32 %0, %1;" : "=f"(y) : "f"(x));
    return y;
}

__device__ __forceinline__ void mma_tf32(float c[4], const uint32_t a[4],
                                         uint32_t b0, uint32_t b1) {
    asm volatile(
        "mma.sync.aligned.m16n8k8.row.col.f32.tf32.tf32.f32 "
        "{%0,%1,%2,%3}, {%4,%5,%6,%7}, {%8,%9}, {%0,%1,%2,%3};"
        : "+f"(c[0]), "+f"(c[1]), "+f"(c[2]), "+f"(c[3])
        : "r"(a[0]), "r"(a[1]), "r"(a[2]), "r"(a[3]), "r"(b0), "r"(b1));
}

__device__ __forceinline__ void ldsm4(uint32_t& d0, uint32_t& d1,
                                      uint32_t& d2, uint32_t& d3,
                                      uint32_t addr) {
    asm volatile("ldmatrix.sync.aligned.m8n8.x4.shared.b16 {%0,%1,%2,%3}, [%4];"
                 : "=r"(d0), "=r"(d1), "=r"(d2), "=r"(d3) : "r"(addr));
}

__device__ __forceinline__ uint32_t smem_u32(const void* p) {
    uint32_t a;
    asm("{ .reg .u64 t; cvta.to.shared.u64 t, %1; cvt.u32.u64 %0, t; }"
        : "=r"(a) : "l"(p));
    return a;
}

__device__ __forceinline__ void cp16(uint32_t dst, const void* src) {
    asm volatile("cp.async.cg.shared.global [%0], [%1], 16;"
                 :: "r"(dst), "l"(src));
}
#define CP_COMMIT() asm volatile("cp.async.commit_group;" ::: "memory")
#define CP_WAIT0()  asm volatile("cp.async.wait_group 0;" ::: "memory")
#define CP_WAIT2()  asm volatile("cp.async.wait_group 2;" ::: "memory")

// ---------------------------------------------------------------------------
// Prepass: tf32-round (rna) x and W into scratch copies.
// ---------------------------------------------------------------------------
__global__ __launch_bounds__(256) void cvt_pre(
    const float* __restrict__ x, const float* __restrict__ W)
{
    const size_t nx = (size_t)M_TOT * C_DIM / 4;
    const size_t nw = (size_t)N_TOT * C_DIM / 4;
    size_t i = (size_t)blockIdx.x * blockDim.x + threadIdx.x;
    if (i < nx) {
        float4 v = ((const float4*)x)[i];
        uint4 u = { f2tf(v.x), f2tf(v.y), f2tf(v.z), f2tf(v.w) };
        ((uint4*)g_xt)[i] = u;
    } else if (i < nx + nw) {
        float4 v = ((const float4*)W)[i - nx];
        uint4 u = { f2tf(v.x), f2tf(v.y), f2tf(v.z), f2tf(v.w) };
        ((uint4*)g_wt)[i - nx] = u;
    }
}

// ---------------------------------------------------------------------------
// QKV GEMM: 4-stage cp.async pipeline, ONE sync per k-tile, ldmatrix frags.
// CTA 128x128, k16, 8 warps (2Mx4N). Inputs pre-rounded (g_xt/g_wt).
// Q/K scattered (tf32-rounded) to [B,H,T,D]; V transposed to [B,H,D,T].
// ---------------------------------------------------------------------------
#define GPAD 20
#define GSTAGE_U32 (128 * GPAD)
#define GEMM_SMEM_BYTES (8 * GSTAGE_U32 * 4)   // (A+B) x 4 stages = 81920 B

__global__ __launch_bounds__(256, 2) void qkv_gemm_tf32(
    const float* __restrict__ b)
{
    extern __shared__ uint32_t gsm[];
    uint32_t* Abuf = gsm;                     // [4][128][GPAD]
    uint32_t* Bbuf = gsm + 4 * GSTAGE_U32;    // [4][128][GPAD]

    const int tid  = threadIdx.x;
    const int lane = tid & 31;
    const int warp = tid >> 5;
    const int wm = warp >> 2;
    const int wn = warp & 3;
    const int m0 = blockIdx.y * 128;
    const int n0 = blockIdx.x * 128;

    const uint32_t aBase = smem_u32(Abuf);
    const uint32_t bBase = smem_u32(Bbuf);

    const uint32_t offA = ((((lane & 7) + ((lane >> 3) & 1) * 8) * GPAD)
                           + (lane >> 4) * 4) * 4;
    const uint32_t offBP = ((((lane & 7) + (lane >> 4) * 8) * GPAD)
                            + ((lane >> 3) & 1) * 4) * 4;

    const int lrow = tid >> 1;
    const int lcol = (tid & 1) * 8;
    const float* ap = g_xt + (size_t)(m0 + lrow) * C_DIM + lcol;
    const float* bp = g_wt + (size_t)(n0 + lrow) * C_DIM + lcol;
    const uint32_t aDst = aBase + (lrow * GPAD + lcol) * 4;
    const uint32_t bDst = bBase + (lrow * GPAD + lcol) * 4;

    float acc[4][4][4] = {};

    // prologue: stages 0..2 in flight
    #pragma unroll
    for (int s = 0; s < 3; s++) {
        const uint32_t so = (uint32_t)s * (GSTAGE_U32 * 4);
        cp16(aDst + so, ap + s * 16);
        cp16(aDst + so + 16, ap + s * 16 + 4);
        cp16(bDst + so, bp + s * 16);
        cp16(bDst + so + 16, bp + s * 16 + 4);
        CP_COMMIT();
    }

    #pragma unroll 1
    for (int kt = 0; kt < 64; kt++) {
        CP_WAIT2();          // tile kt landed
        __syncthreads();     // visible to all; stage (kt+3)&3 readers done

        if (kt + 3 < 64) {
            const int kn = kt + 3;
            const uint32_t so = (uint32_t)(kn & 3) * (GSTAGE_U32 * 4);
            cp16(aDst + so, ap + kn * 16);
            cp16(aDst + so + 16, ap + kn * 16 + 4);
            cp16(bDst + so, bp + kn * 16);
            cp16(bDst + so + 16, bp + kn * 16 + 4);
        }
        CP_COMMIT();

        const uint32_t soff = (uint32_t)(kt & 3) * (GSTAGE_U32 * 4);
        #pragma unroll
        for (int ks = 0; ks < 16; ks += 8) {
            uint32_t af[4][4];
            #pragma unroll
            for (int mt = 0; mt < 4; mt++) {
                ldsm4(af[mt][0], af[mt][1], af[mt][2], af[mt][3],
                      aBase + soff + ((wm * 64 + mt * 16) * GPAD + ks) * 4 + offA);
            }
            uint32_t bf[4][2];
            ldsm4(bf[0][0], bf[0][1], bf[1][0], bf[1][1],
                  bBase + soff + ((wn * 32) * GPAD + ks) * 4 + offBP);
            ldsm4(bf[2][0], bf[2][1], bf[3][0], bf[3][1],
                  bBase + soff + ((wn * 32 + 16) * GPAD + ks) * 4 + offBP);
            #pragma unroll
            for (int mt = 0; mt < 4; mt++)
                #pragma unroll
                for (int nt = 0; nt < 4; nt++)
                    mma_tf32(acc[mt][nt], af[mt], bf[nt][0], bf[nt][1]);
        }
    }

    const int which = n0 >> 10;
    const int bq = m0 >> 11;
    const int t0 = m0 & (T_DIM - 1);
    const int h  = (((n0 & 1023) + wn * 32) >> 6);

    if (which < 2) {
        float* dst = (which == 0) ? g_q : g_k;
        #pragma unroll
        for (int nt = 0; nt < 4; nt++) {
            const int ncol = wn * 32 + nt * 8 + 2 * (lane & 3);
            const float2 bias = *(const float2*)(b + n0 + ncol);
            const int d = ncol & 63;
            const size_t rowbase = (size_t)(bq * H_DIM + h) * T_DIM;
            #pragma unroll
            for (int mt = 0; mt < 4; mt++) {
                const int t = t0 + wm * 64 + mt * 16 + (lane >> 2);
                float2 v0 = { __uint_as_float(f2tf(acc[mt][nt][0] + bias.x)),
                              __uint_as_float(f2tf(acc[mt][nt][1] + bias.y)) };
                float2 v1 = { __uint_as_float(f2tf(acc[mt][nt][2] + bias.x)),
                              __uint_as_float(f2tf(acc[mt][nt][3] + bias.y)) };
                *(float2*)(dst + (rowbase + t) * HD + d)     = v0;
                *(float2*)(dst + (rowbase + t + 8) * HD + d) = v1;
            }
        }
    } else {
        // V: transposed scatter (tf32-rounded) to [B,H,D,T]
        const size_t hb = (size_t)(bq * H_DIM + h) * HD;
        #pragma unroll
        for (int nt = 0; nt < 4; nt++) {
            const int ncol = wn * 32 + nt * 8 + 2 * (lane & 3);
            const float2 bias = *(const float2*)(b + n0 + ncol);
            const int d = ncol & 63;
            float* r0 = g_v + (hb + d)     * T_DIM;
            float* r1 = g_v + (hb + d + 1) * T_DIM;
            #pragma unroll
            for (int mt = 0; mt < 4; mt++) {
                const int t = t0 + wm * 64 + mt * 16 + (lane >> 2);
                r0[t]     = __uint_as_float(f2tf(acc[mt][nt][0] + bias.x));
                r1[t]     = __uint_as_float(f2tf(acc[mt][nt][1] + bias.y));
                r0[t + 8] = __uint_as_float(f2tf(acc[mt][nt][2] + bias.x));
                r1[t + 8] = __uint_as_float(f2tf(acc[mt][nt][3] + bias.y));
            }
        }
    }
}

// ---------------------------------------------------------------------------
// Flash attention: 128 q-rows/CTA, 4 warps x 32 rows. KV tiles of 64,
// DOUBLE-BUFFERED via cp.async (1-tile lookahead), ONE sync per tile.
// Softmax scale folded into ex2 (Q copied raw; data pre-tf32-rounded).
// ---------------------------------------------------------------------------
#define APAD 68
#define KV_U32 (64 * APAD)
#define SMEM_U32 (4 * KV_U32 + 128 * APAD)   // Ks[2],Vt[2],Ps
#define ATTN_SMEM_BYTES (SMEM_U32 * 4)
#define SC 0.1803368801111204f   // (1/8) * log2(e)

__global__ __launch_bounds__(128, 2) void attn_tf32(float* __restrict__ out)
{
    extern __shared__ uint32_t sm[];
    // [0 .. 2*KV_U32): Ks[2]; [2*KV_U32 .. 4*KV_U32): Vt[2]; then Ps[128][APAD]
    const uint32_t ksBase = smem_u32(sm);
    const uint32_t vtBase = ksBase + 2 * KV_U32 * 4;
    const uint32_t psBase = ksBase + 4 * KV_U32 * 4;
    uint32_t (*Ps)[APAD] = (uint32_t(*)[APAD])(sm + 4 * KV_U32);

    const int tid  = threadIdx.x;
    const int lane = tid & 31;
    const int warp = tid >> 5;
    const int qt = (gridDim.x - 1) - blockIdx.x;   // heavy tiles first
    const int bh = blockIdx.y;

    const uint32_t offA = ((((lane & 7) + ((lane >> 3) & 1) * 8) * APAD)
                           + (lane >> 4) * 4) * 4;
    const uint32_t offB = (((lane & 7) * APAD) + (lane >> 3) * 4) * 4;

    const float* Qg  = g_q + (size_t)bh * T_DIM * HD;
    const float* Kg  = g_k + (size_t)bh * T_DIM * HD;
    const float* Vgt = g_v + (size_t)bh * HD * T_DIM;

    const int srow = tid >> 1;           // 0..63
    const int ch   = (tid & 1) * 32;     // 0 or 32
    const uint32_t kDst = ksBase + (srow * APAD + ch) * 4;
    const uint32_t vDst = vtBase + (srow * APAD + ch) * 4;

    // ---- stage Q raw (pre-rounded), pull qa fragments ----
    {
        const uint4* qp = (const uint4*)(Qg + (size_t)(qt * 128 + tid) * HD);
        #pragma unroll
        for (int i = 0; i < 16; i++) *(uint4*)&Ps[tid][i * 4] = qp[i];
    }
    // ---- prologue: KV tile 0 in flight ----
    {
        const float* kp = Kg  + (size_t)srow * HD + ch;
        const float* vp = Vgt + (size_t)srow * T_DIM + ch;
        #pragma unroll
        for (int i = 0; i < 8; i++) {
            cp16(kDst + i * 16, kp + i * 4);
            cp16(vDst + i * 16, vp + i * 4);
        }
        CP_COMMIT();
    }
    __syncwarp();
    uint32_t qa[2][8][4];
    #pragma unroll
    for (int mt = 0; mt < 2; mt++)
        #pragma unroll
        for (int k = 0; k < 8; k++)
            ldsm4(qa[mt][k][0], qa[mt][k][1], qa[mt][k][2], qa[mt][k][3],
                  psBase + ((warp * 32 + mt * 16) * APAD + k * 8) * 4 + offA);

    float oa[2][8][4] = {};
    float mr[2][2] = {{-1e30f, -1e30f}, {-1e30f, -1e30f}};
    float lv[2][2] = {};
    const int rbase = qt * 128 + warp * 32;
    const int NKV = 2 * qt + 2;

    for (int kt = 0; kt < NKV; kt++) {
        CP_WAIT0();          // tile kt landed
        __syncthreads();     // visible; prior readers of buf (kt+1)&1 done

        if (kt + 1 < NKV) {
            const int kn = kt + 1;
            const uint32_t bo = (uint32_t)(kn & 1) * (KV_U32 * 4);
            const float* kp = Kg  + (size_t)(kn * 64 + srow) * HD + ch;
            const float* vp = Vgt + (size_t)srow * T_DIM + kn * 64 + ch;
            #pragma unroll
            for (int i = 0; i < 8; i++) {
                cp16(kDst + bo + i * 16, kp + i * 4);
                cp16(vDst + bo + i * 16, vp + i * 4);
            }
        }
        CP_COMMIT();

        // warps whose rows are fully masked skip compute (still hit barriers)
        if (kt * 64 > rbase + 31) continue;

        const uint32_t bo = (uint32_t)(kt & 1) * (KV_U32 * 4);

        // ---- S = Q @ K^T ----
        float s[2][8][4] = {};
        #pragma unroll
        for (int kp2 = 0; kp2 < 4; kp2++) {
            #pragma unroll
            for (int j = 0; j < 8; j++) {
                uint32_t b0, b1, b2, b3;
                ldsm4(b0, b1, b2, b3,
                      ksBase + bo + ((j * 8) * APAD + kp2 * 16) * 4 + offB);
                mma_tf32(s[0][j], qa[0][2 * kp2],     b0, b1);
                mma_tf32(s[0][j], qa[0][2 * kp2 + 1], b2, b3);
                mma_tf32(s[1][j], qa[1][2 * kp2],     b0, b1);
                mma_tf32(s[1][j], qa[1][2 * kp2 + 1], b2, b3);
            }
        }

        // ---- causal mask (diagonal-overlapping tiles) ----
        if (kt * 64 + 63 > rbase) {
            #pragma unroll
            for (int mt = 0; mt < 2; mt++) {
                const int gr0 = rbase + mt * 16 + (lane >> 2);
                const int gr1 = gr0 + 8;
                #pragma unroll
                for (int j = 0; j < 8; j++) {
                    const int c0 = kt * 64 + j * 8 + 2 * (lane & 3);
                    if (c0     > gr0) s[mt][j][0] = -1e30f;
                    if (c0 + 1 > gr0) s[mt][j][1] = -1e30f;
                    if (c0     > gr1) s[mt][j][2] = -1e30f;
                    if (c0 + 1 > gr1) s[mt][j][3] = -1e30f;
                }
            }
        }

        // ---- online softmax (raw-logit max; scale folded into ex2) ----
        #pragma unroll
        for (int mt = 0; mt < 2; mt++) {
            float mx0 = -1e30f, mx1 = -1e30f;
            #pragma unroll
            for (int j = 0; j < 8; j++) {
                mx0 = fmaxf(mx0, fmaxf(s[mt][j][0], s[mt][j][1]));
                mx1 = fmaxf(mx1, fmaxf(s[mt][j][2], s[mt][j][3]));
            }
            mx0 = fmaxf(mx0, __shfl_xor_sync(0xffffffff, mx0, 1));
            mx0 = fmaxf(mx0, __shfl_xor_sync(0xffffffff, mx0, 2));
            mx1 = fmaxf(mx1, __shfl_xor_sync(0xffffffff, mx1, 1));
            mx1 = fmaxf(mx1, __shfl_xor_sync(0xffffffff, mx1, 2));

            const float nm0 = fmaxf(mr[mt][0], mx0);
            const float nm1 = fmaxf(mr[mt][1], mx1);
            const float nm0c = nm0 * SC;
            const float nm1c = nm1 * SC;
            const float corr0 = ex2(fmaf(mr[mt][0], SC, -nm0c));
            const float corr1 = ex2(fmaf(mr[mt][1], SC, -nm1c));
            mr[mt][0] = nm0; mr[mt][1] = nm1;

            float sum0 = 0.0f, sum1 = 0.0f;
            #pragma unroll
            for (int j = 0; j < 8; j++) {
                s[mt][j][0] = ex2(fmaf(s[mt][j][0], SC, -nm0c)); sum0 += s[mt][j][0];
                s[mt][j][1] = ex2(fmaf(s[mt][j][1], SC, -nm0c)); sum0 += s[mt][j][1];
                s[mt][j][2] = ex2(fmaf(s[mt][j][2], SC, -nm1c)); sum1 += s[mt][j][2];
                s[mt][j][3] = ex2(fmaf(s[mt][j][3], SC, -nm1c)); sum1 += s[mt][j][3];
            }
            sum0 += __shfl_xor_sync(0xffffffff, sum0, 1);
            sum0 += __shfl_xor_sync(0xffffffff, sum0, 2);
            sum1 += __shfl_xor_sync(0xffffffff, sum1, 1);
            sum1 += __shfl_xor_sync(0xffffffff, sum1, 2);
            lv[mt][0] = lv[mt][0] * corr0 + sum0;
            lv[mt][1] = lv[mt][1] * corr1 + sum1;

            #pragma unroll
            for (int j = 0; j < 8; j++) {
                oa[mt][j][0] *= corr0; oa[mt][j][1] *= corr0;
                oa[mt][j][2] *= corr1; oa[mt][j][3] *= corr1;
            }

            // store P (warp-private rows)
            const int r = warp * 32 + mt * 16 + (lane >> 2);
            #pragma unroll
            for (int j = 0; j < 8; j++) {
                const int c = j * 8 + 2 * (lane & 3);
                uint2 u0 = { f2tf(s[mt][j][0]), f2tf(s[mt][j][1]) };
                uint2 u1 = { f2tf(s[mt][j][2]), f2tf(s[mt][j][3]) };
                *(uint2*)&Ps[r][c]     = u0;
                *(uint2*)&Ps[r + 8][c] = u1;
            }
        }
        __syncwarp();

        // ---- O += P @ V ----
        #pragma unroll
        for (int kp2 = 0; kp2 < 4; kp2++) {
            uint32_t a0[4], a1[4], a2[4], a3[4];
            ldsm4(a0[0], a0[1], a0[2], a0[3],
                  psBase + ((warp * 32) * APAD + kp2 * 16) * 4 + offA);
            ldsm4(a1[0], a1[1], a1[2], a1[3],
                  psBase + ((warp * 32) * APAD + kp2 * 16 + 8) * 4 + offA);
            ldsm4(a2[0], a2[1], a2[2], a2[3],
                  psBase + ((warp * 32 + 16) * APAD + kp2 * 16) * 4 + offA);
            ldsm4(a3[0], a3[1], a3[2], a3[3],
                  psBase + ((warp * 32 + 16) * APAD + kp2 * 16 + 8) * 4 + offA);
            #pragma unroll
            for (int j = 0; j < 8; j++) {
                uint32_t b0, b1, b2, b3;
                ldsm4(b0, b1, b2, b3,
                      vtBase + bo + ((j * 8) * APAD + kp2 * 16) * 4 + offB);
                mma_tf32(oa[0][j], a0, b0, b1);
                mma_tf32(oa[0][j], a1, b2, b3);
                mma_tf32(oa[1][j], a2, b0, b1);
                mma_tf32(oa[1][j], a3, b2, b3);
            }
        }
    }

    // ---- epilogue: normalize, write [B,T,C] ----
    const int bq = bh >> 4;
    const int h  = bh & 15;
    #pragma unroll
    for (int mt = 0; mt < 2; mt++) {
        const float inv0 = 1.0f / lv[mt][0];
        const float inv1 = 1.0f / lv[mt][1];
        const int trow = rbase + mt * 16 + (lane >> 2);
        #pragma unroll
        for (int j = 0; j < 8; j++) {
            const int d = j * 8 + 2 * (lane & 3);
            float2 v0 = { oa[mt][j][0] * inv0, oa[mt][j][1] * inv0 };
            float2 v1 = { oa[mt][j][2] * inv1, oa[mt][j][3] * inv1 };
            *(float2*)(out + (size_t)(bq * T_DIM + trow) * C_DIM + h * HD + d)     = v0;
            *(float2*)(out + (size_t)(bq * T_DIM + trow + 8) * C_DIM + h * HD + d) = v1;
        }
    }
}

// ---------------------------------------------------------------------------
extern "C" void kernel_launch(void* const* d_in, const int* in_sizes, int n_in,
                              void* d_out, int out_size)
{
    const float* x = (const float*)d_in[0];   // [4, 2048, 1024]
    const float* W = (const float*)d_in[1];   // [3072, 1024]
    const float* b = (const float*)d_in[2];   // [3072]
    float* out = (float*)d_out;               // [4, 2048, 1024]

    cudaFuncSetAttribute(qkv_gemm_tf32, cudaFuncAttributeMaxDynamicSharedMemorySize,
                         GEMM_SMEM_BYTES);
    cudaFuncSetAttribute(attn_tf32, cudaFuncAttributeMaxDynamicSharedMemorySize,
                         ATTN_SMEM_BYTES);

    const size_t ncvt = ((size_t)M_TOT * C_DIM + (size_t)N_TOT * C_DIM) / 4;
    cvt_pre<<<(unsigned)((ncvt + 255) / 256), 256>>>(x, W);
    qkv_gemm_tf32<<<dim3(N_TOT / 128, M_TOT / 128), 256, GEMM_SMEM_BYTES>>>(b);
    attn_tf32<<<dim3(T_DIM / 128, B_DIM * H_DIM), 128, ATTN_SMEM_BYTES>>>(out);
}